// round 1
// baseline (speedup 1.0000x reference)
#include <cuda_runtime.h>
#include <cuda_bf16.h>
#include <math.h>

// ---------------- problem constants ----------------
#define B_      64
#define T_      512
#define WIN_    40
#define KS_     3
#define NPT_    9          // KS*KS
#define CF_     8
#define H_      510        // T - 2
#define WO_     38         // WIN - 2
#define GIN_    304        // WO_*CF_
#define GH_     32
#define G3_     96         // 3*GH
#define ATTN_   32
#define NTOK_   (H_ * B_)  // 32640

// ---------------- scratch (device globals; no cudaMalloc allowed) -------------
__device__ float g_seq[NTOK_ * GIN_];   // (t,b,f)  f = w*8 + c
__device__ float g_xp [NTOK_ * G3_];    // (t,b,g)
__device__ float g_enc[B_ * H_ * GH_];  // (b,t,g)
__device__ float g_att[B_ * H_ * GH_];  // (b,t,g)

// ---------------- activations ----------------
__device__ __forceinline__ float fsig(float x) {
    return 1.0f / (1.0f + __expf(-x));
}
__device__ __forceinline__ float ftanh(float x) {
    float e = __expf(-2.0f * fabsf(x));
    float t = (1.0f - e) / (1.0f + e);
    return copysignf(t, x);
}

// =====================================================================
// Kernel 1: deformable conv -> g_seq (t,b, w*8+c)
// one thread per output pixel (b,t,w)
// =====================================================================
__global__ void k_deform(const float* __restrict__ x,
                         const float* __restrict__ p_w,
                         const float* __restrict__ p_b,
                         const float* __restrict__ dcn_w,
                         const float* __restrict__ dcn_b)
{
    __shared__ float s_pw[2 * NPT_ * NPT_];  // 162
    __shared__ float s_pb[2 * NPT_];         // 18
    __shared__ float s_dw[CF_ * NPT_];       // 72
    __shared__ float s_db[CF_];

    int tid = threadIdx.x;
    for (int i = tid; i < 2 * NPT_ * NPT_; i += blockDim.x) s_pw[i] = p_w[i];
    for (int i = tid; i < 2 * NPT_;       i += blockDim.x) s_pb[i] = p_b[i];
    for (int i = tid; i < CF_ * NPT_;     i += blockDim.x) s_dw[i] = dcn_w[i];
    for (int i = tid; i < CF_;            i += blockDim.x) s_db[i] = dcn_b[i];
    __syncthreads();

    int idx = blockIdx.x * blockDim.x + tid;
    const int total = B_ * H_ * WO_;
    if (idx >= total) return;

    int w  = idx % WO_;
    int b  = (idx / WO_) % B_;
    int t  = idx / (WO_ * B_);

    const float* xb = x + b * (T_ * WIN_);

    // 3x3 patch at (t..t+2, w..w+2)
    float patch[NPT_];
#pragma unroll
    for (int ky = 0; ky < KS_; ky++)
#pragma unroll
        for (int kx = 0; kx < KS_; kx++)
            patch[ky * KS_ + kx] = xb[(t + ky) * WIN_ + (w + kx)];

    // 18 offsets
    float off[2 * NPT_];
#pragma unroll
    for (int o = 0; o < 2 * NPT_; o++) off[o] = s_pb[o];
#pragma unroll
    for (int k = 0; k < NPT_; k++) {
        float pv = patch[k];
#pragma unroll
        for (int o = 0; o < 2 * NPT_; o++)
            off[o] = fmaf(pv, s_pw[o * NPT_ + k], off[o]);
    }

    float acc[CF_];
#pragma unroll
    for (int c = 0; c < CF_; c++) acc[c] = s_db[c];

#pragma unroll
    for (int n = 0; n < NPT_; n++) {
        float py = off[n]        + (float)(n / 3 - 1) + (float)(t + 1);
        float px = off[NPT_ + n] + (float)(n % 3 - 1) + (float)(w + 1);
        py = fminf(fmaxf(py, 0.0f), (float)(T_ - 1));
        px = fminf(fmaxf(px, 0.0f), (float)(WIN_ - 1));
        int y0 = (int)floorf(py);
        int x0 = (int)floorf(px);
        int y1 = min(y0 + 1, T_ - 1);
        int x1 = min(x0 + 1, WIN_ - 1);
        float wy = py - (float)y0;
        float wx = px - (float)x0;
        float g00 = __ldg(&xb[y0 * WIN_ + x0]);
        float g01 = __ldg(&xb[y0 * WIN_ + x1]);
        float g10 = __ldg(&xb[y1 * WIN_ + x0]);
        float g11 = __ldg(&xb[y1 * WIN_ + x1]);
        float top = g00 + wx * (g01 - g00);
        float bot = g10 + wx * (g11 - g10);
        float s   = top + wy * (bot - top);
#pragma unroll
        for (int c = 0; c < CF_; c++)
            acc[c] = fmaf(s, s_dw[c * NPT_ + n], acc[c]);
    }

    // seq[t][b][w*8 + c]
    float* dst = g_seq + (size_t)(t * B_ + b) * GIN_ + w * CF_;
    float4 v0 = make_float4(acc[0], acc[1], acc[2], acc[3]);
    float4 v1 = make_float4(acc[4], acc[5], acc[6], acc[7]);
    *reinterpret_cast<float4*>(dst)     = v0;
    *reinterpret_cast<float4*>(dst + 4) = v1;
}

// =====================================================================
// Kernel 2: xp[tok][g] = seq[tok][:] . w_ih[g][:] + b_ih[g]
// block = 8 tokens x 96 outputs, 96 threads; shared token data transposed
// =====================================================================
#define TOKPB 8
__global__ void k_gemm(const float* __restrict__ w_ih,
                       const float* __restrict__ b_ih)
{
    __shared__ float sh[GIN_ * TOKPB];   // [f][tok]
    int tid = threadIdx.x;               // 0..95 = g
    int base = blockIdx.x * TOKPB;

    for (int i = tid; i < GIN_ * TOKPB; i += G3_) {
        int tok = i / GIN_;
        int f   = i - tok * GIN_;
        sh[f * TOKPB + tok] = g_seq[(size_t)(base + tok) * GIN_ + f];
    }
    __syncthreads();

    const float* wr = w_ih + tid * GIN_;
    float acc[TOKPB];
#pragma unroll
    for (int k = 0; k < TOKPB; k++) acc[k] = 0.0f;

#pragma unroll 4
    for (int f = 0; f < GIN_; f++) {
        float wv = __ldg(&wr[f]);
        float4 a0 = *reinterpret_cast<const float4*>(&sh[f * TOKPB]);
        float4 a1 = *reinterpret_cast<const float4*>(&sh[f * TOKPB + 4]);
        acc[0] = fmaf(a0.x, wv, acc[0]);
        acc[1] = fmaf(a0.y, wv, acc[1]);
        acc[2] = fmaf(a0.z, wv, acc[2]);
        acc[3] = fmaf(a0.w, wv, acc[3]);
        acc[4] = fmaf(a1.x, wv, acc[4]);
        acc[5] = fmaf(a1.y, wv, acc[5]);
        acc[6] = fmaf(a1.z, wv, acc[6]);
        acc[7] = fmaf(a1.w, wv, acc[7]);
    }

    float bias = __ldg(&b_ih[tid]);
#pragma unroll
    for (int k = 0; k < TOKPB; k++)
        g_xp[(size_t)(base + k) * G3_ + tid] = acc[k] + bias;
}

// =====================================================================
// Kernel 3: GRU scan. 1 warp per batch. lane l owns h[l].
// =====================================================================
__global__ void k_gru(const float* __restrict__ w_hh,
                      const float* __restrict__ b_hh)
{
    int b = blockIdx.x;
    int l = threadIdx.x;   // 0..31

    float wr[GH_], wz[GH_], wn[GH_];
#pragma unroll
    for (int k = 0; k < GH_; k++) {
        wr[k] = w_hh[(0 * GH_ + l) * GH_ + k];
        wz[k] = w_hh[(1 * GH_ + l) * GH_ + k];
        wn[k] = w_hh[(2 * GH_ + l) * GH_ + k];
    }
    float br = b_hh[l], bz = b_hh[GH_ + l], bn = b_hh[2 * GH_ + l];

    float h = 0.0f;
    const float* xpb = g_xp + b * G3_;
    float* encb = g_enc + (size_t)b * H_ * GH_;

    // prefetch t=0
    float xr = xpb[l], xz = xpb[GH_ + l], xn = xpb[2 * GH_ + l];

    for (int t = 0; t < H_; t++) {
        // prefetch next step's x
        float nxr = 0.f, nxz = 0.f, nxn = 0.f;
        if (t + 1 < H_) {
            const float* xt = xpb + (size_t)(t + 1) * (B_ * G3_);
            nxr = xt[l]; nxz = xt[GH_ + l]; nxn = xt[2 * GH_ + l];
        }

        float ar = br, az = bz, an = bn;
#pragma unroll
        for (int k = 0; k < GH_; k++) {
            float hv = __shfl_sync(0xffffffffu, h, k);
            ar = fmaf(hv, wr[k], ar);
            az = fmaf(hv, wz[k], az);
            an = fmaf(hv, wn[k], an);
        }
        float rg = fsig(xr + ar);
        float zg = fsig(xz + az);
        float ng = ftanh(fmaf(rg, an, xn));
        h = fmaf(zg, h - ng, ng);   // (1-zg)*ng + zg*h

        encb[t * GH_ + l] = h;
        xr = nxr; xz = nxz; xn = nxn;
    }
}

// =====================================================================
// Kernel 4: attention + head. block per batch, 256 threads.
// =====================================================================
__global__ void k_attn(const float* __restrict__ w1, const float* __restrict__ b1,
                       const float* __restrict__ w2, const float* __restrict__ b2,
                       const float* __restrict__ w3, const float* __restrict__ b3,
                       float* __restrict__ out)
{
    int b    = blockIdx.x;
    int tid  = threadIdx.x;
    int lane = tid & 31;
    int part = tid >> 5;        // 0..7 (warp id)

    const float* encb = g_enc + (size_t)b * H_ * GH_;
    float*       attb = g_att + (size_t)b * H_ * GH_;

    // per-lane weight rows
    float w1r[GH_], w2r[GH_];
#pragma unroll
    for (int k = 0; k < GH_; k++) {
        w1r[k] = w1[lane * GH_ + k];
        w2r[k] = w2[lane * GH_ + k];
    }
    float b1l = b1[lane], b2l = b2[lane];

    // phase A: scores a[t][g]
    for (int t = part; t < H_; t += 8) {
        float e = encb[t * GH_ + lane];
        float acch = b1l;
#pragma unroll
        for (int k = 0; k < GH_; k++)
            acch = fmaf(__shfl_sync(0xffffffffu, e, k), w1r[k], acch);
        float hid = ftanh(acch);
        float acca = b2l;
#pragma unroll
        for (int k = 0; k < GH_; k++)
            acca = fmaf(__shfl_sync(0xffffffffu, hid, k), w2r[k], acca);
        attb[t * GH_ + lane] = acca;
    }
    __syncthreads();

    // phase B: softmax over t + weighted pool, per channel g
    __shared__ float redm[8][GH_];
    __shared__ float reds[8][GH_];
    __shared__ float redp[8][GH_];
    __shared__ float pooled[GH_];

    int g = lane;
    float m = -1e30f;
    for (int t = part; t < H_; t += 8)
        m = fmaxf(m, attb[t * GH_ + g]);
    redm[part][g] = m;
    __syncthreads();
    float mg = redm[0][g];
#pragma unroll
    for (int p = 1; p < 8; p++) mg = fmaxf(mg, redm[p][g]);

    float se = 0.0f, pw = 0.0f;
    for (int t = part; t < H_; t += 8) {
        float ex = __expf(attb[t * GH_ + g] - mg);
        se += ex;
        pw = fmaf(ex, encb[t * GH_ + g], pw);
    }
    reds[part][g] = se;
    redp[part][g] = pw;
    __syncthreads();
    if (part == 0) {
        float ts = 0.0f, tp = 0.0f;
#pragma unroll
        for (int p = 0; p < 8; p++) { ts += reds[p][g]; tp += redp[p][g]; }
        pooled[g] = tp / ts;
    }
    __syncthreads();

    // phase C: out[b][o] = pooled . w3[o] + b3[o]
    if (tid < 64) {
        int o  = tid >> 5;
        int gg = tid & 31;
        float v = pooled[gg] * w3[o * GH_ + gg];
#pragma unroll
        for (int s = 16; s > 0; s >>= 1)
            v += __shfl_xor_sync(0xffffffffu, v, s);
        if (gg == 0)
            out[b * 2 + o] = v + b3[o];
    }
}

// =====================================================================
extern "C" void kernel_launch(void* const* d_in, const int* in_sizes, int n_in,
                              void* d_out, int out_size)
{
    const float* x     = (const float*)d_in[0];
    const float* p_w   = (const float*)d_in[1];
    const float* p_b   = (const float*)d_in[2];
    const float* dcn_w = (const float*)d_in[3];
    const float* dcn_b = (const float*)d_in[4];
    const float* w_ih  = (const float*)d_in[5];
    const float* w_hh  = (const float*)d_in[6];
    const float* b_ih  = (const float*)d_in[7];
    const float* b_hh  = (const float*)d_in[8];
    const float* w1    = (const float*)d_in[9];
    const float* b1    = (const float*)d_in[10];
    const float* w2    = (const float*)d_in[11];
    const float* b2    = (const float*)d_in[12];
    const float* w3    = (const float*)d_in[13];
    const float* b3    = (const float*)d_in[14];
    float* out = (float*)d_out;

    {
        int total  = B_ * H_ * WO_;
        int threads = 128;
        int blocks  = (total + threads - 1) / threads;
        k_deform<<<blocks, threads>>>(x, p_w, p_b, dcn_w, dcn_b);
    }
    {
        int blocks = NTOK_ / TOKPB;   // 4080
        k_gemm<<<blocks, G3_>>>(w_ih, b_ih);
    }
    {
        k_gru<<<B_, GH_>>>(w_hh, b_hh);
    }
    {
        k_attn<<<B_, 256>>>(w1, b1, w2, b2, w3, b3, out);
    }
}

// round 2
// speedup vs baseline: 1.4598x; 1.4598x over previous
#include <cuda_runtime.h>
#include <cuda_bf16.h>
#include <math.h>

// ---------------- problem constants ----------------
#define B_      64
#define T_      512
#define WIN_    40
#define KS_     3
#define NPT_    9          // KS*KS
#define CF_     8
#define H_      510        // T - 2
#define WO_     38         // WIN - 2
#define GIN_    304        // WO_*CF_
#define GH_     32
#define G3_     96         // 3*GH
#define NTOK_   (H_ * B_)  // 32640

typedef unsigned long long ull;

// ---------------- scratch (device globals; no cudaMalloc allowed) -------------
__device__ float g_seq[NTOK_ * GIN_];   // (t,b,f)  f = w*8 + c
__device__ float g_xp [NTOK_ * G3_];    // (t,b,g)
__device__ float g_enc[B_ * H_ * GH_];  // (b,t,g)
__device__ float g_att[B_ * H_ * GH_];  // (b,t,g)

// ---------------- f32x2 packed math helpers ----------------
__device__ __forceinline__ ull ffma2(ull a, ull b, ull c) {
    ull d;
    asm("fma.rn.f32x2 %0, %1, %2, %3;" : "=l"(d) : "l"(a), "l"(b), "l"(c));
    return d;
}
__device__ __forceinline__ ull pack2(float x, float y) {
    ull v;
    asm("mov.b64 %0, {%1, %2};" : "=l"(v) : "f"(x), "f"(y));
    return v;
}
__device__ __forceinline__ float2 unpack2(ull v) {
    float2 r;
    asm("mov.b64 {%0, %1}, %2;" : "=f"(r.x), "=f"(r.y) : "l"(v));
    return r;
}

// ---------------- activations (expf-based: ~1e-7 err, proven) -----------
__device__ __forceinline__ float fsig(float x) {
    return 1.0f / (1.0f + __expf(-x));
}
__device__ __forceinline__ float ftanh(float x) {
    float e = __expf(-2.0f * fabsf(x));
    float t = (1.0f - e) / (1.0f + e);
    return copysignf(t, x);
}

// =====================================================================
// Kernel 1: deformable conv -> g_seq (t,b, w*8+c)
// =====================================================================
__global__ void k_deform(const float* __restrict__ x,
                         const float* __restrict__ p_w,
                         const float* __restrict__ p_b,
                         const float* __restrict__ dcn_w,
                         const float* __restrict__ dcn_b)
{
    __shared__ float s_pw[2 * NPT_ * NPT_];
    __shared__ float s_pb[2 * NPT_];
    __shared__ float s_dw[CF_ * NPT_];
    __shared__ float s_db[CF_];

    int tid = threadIdx.x;
    for (int i = tid; i < 2 * NPT_ * NPT_; i += blockDim.x) s_pw[i] = p_w[i];
    for (int i = tid; i < 2 * NPT_;       i += blockDim.x) s_pb[i] = p_b[i];
    for (int i = tid; i < CF_ * NPT_;     i += blockDim.x) s_dw[i] = dcn_w[i];
    for (int i = tid; i < CF_;            i += blockDim.x) s_db[i] = dcn_b[i];
    __syncthreads();

    int idx = blockIdx.x * blockDim.x + tid;
    const int total = B_ * H_ * WO_;
    if (idx >= total) return;

    int w  = idx % WO_;
    int b  = (idx / WO_) % B_;
    int t  = idx / (WO_ * B_);

    const float* xb = x + b * (T_ * WIN_);

    float patch[NPT_];
#pragma unroll
    for (int ky = 0; ky < KS_; ky++)
#pragma unroll
        for (int kx = 0; kx < KS_; kx++)
            patch[ky * KS_ + kx] = xb[(t + ky) * WIN_ + (w + kx)];

    float off[2 * NPT_];
#pragma unroll
    for (int o = 0; o < 2 * NPT_; o++) off[o] = s_pb[o];
#pragma unroll
    for (int k = 0; k < NPT_; k++) {
        float pv = patch[k];
#pragma unroll
        for (int o = 0; o < 2 * NPT_; o++)
            off[o] = fmaf(pv, s_pw[o * NPT_ + k], off[o]);
    }

    float acc[CF_];
#pragma unroll
    for (int c = 0; c < CF_; c++) acc[c] = s_db[c];

#pragma unroll
    for (int n = 0; n < NPT_; n++) {
        float py = off[n]        + (float)(n / 3 - 1) + (float)(t + 1);
        float px = off[NPT_ + n] + (float)(n % 3 - 1) + (float)(w + 1);
        py = fminf(fmaxf(py, 0.0f), (float)(T_ - 1));
        px = fminf(fmaxf(px, 0.0f), (float)(WIN_ - 1));
        int y0 = (int)floorf(py);
        int x0 = (int)floorf(px);
        int y1 = min(y0 + 1, T_ - 1);
        int x1 = min(x0 + 1, WIN_ - 1);
        float wy = py - (float)y0;
        float wx = px - (float)x0;
        float g00 = __ldg(&xb[y0 * WIN_ + x0]);
        float g01 = __ldg(&xb[y0 * WIN_ + x1]);
        float g10 = __ldg(&xb[y1 * WIN_ + x0]);
        float g11 = __ldg(&xb[y1 * WIN_ + x1]);
        float top = g00 + wx * (g01 - g00);
        float bot = g10 + wx * (g11 - g10);
        float s   = top + wy * (bot - top);
#pragma unroll
        for (int c = 0; c < CF_; c++)
            acc[c] = fmaf(s, s_dw[c * NPT_ + n], acc[c]);
    }

    float* dst = g_seq + (size_t)(t * B_ + b) * GIN_ + w * CF_;
    *reinterpret_cast<float4*>(dst)     = make_float4(acc[0], acc[1], acc[2], acc[3]);
    *reinterpret_cast<float4*>(dst + 4) = make_float4(acc[4], acc[5], acc[6], acc[7]);
}

// =====================================================================
// Kernel 2: GEMM 32640x96x304 with fma.rn.f32x2 (packed tokens)
// block: 64 tokens x 96 g, 128 threads; thread: 8 tokens x 6 g
// smem: a transposed [k][tok], w duplicated [k][2g,2g+1]
// =====================================================================
#define TM_ 64
#define KT_ 16
__global__ void __launch_bounds__(128) k_gemm(const float* __restrict__ w_ih,
                                              const float* __restrict__ b_ih)
{
    __shared__ __align__(16) float sa[KT_][TM_];    // 4 KB
    __shared__ __align__(16) float sw[KT_][2 * G3_]; // 12 KB (dup'd)

    int tid = threadIdx.x;
    int tg  = tid >> 4;          // 0..7  -> token group
    int gg  = tid & 15;          // 0..15 -> g group
    int tb  = tg * 8;
    int gbase = gg * 6;
    int base = blockIdx.x * TM_;

    float bias[6];
#pragma unroll
    for (int j = 0; j < 6; j++) bias[j] = __ldg(&b_ih[gbase + j]);

    ull acc[4][6];
#pragma unroll
    for (int p = 0; p < 4; p++)
#pragma unroll
        for (int j = 0; j < 6; j++) acc[p][j] = 0ull;

    for (int kt = 0; kt < GIN_ / KT_; kt++) {
        int k0 = kt * KT_;
        // stage A tile: 64 tok x 16 k, transposed
#pragma unroll
        for (int q = 0; q < 2; q++) {
            int i   = q * 128 + tid;
            int tok = i >> 2;
            int kq  = (i & 3) * 4;
            float4 v = *reinterpret_cast<const float4*>(
                g_seq + (size_t)(base + tok) * GIN_ + k0 + kq);
            sa[kq + 0][tok] = v.x;
            sa[kq + 1][tok] = v.y;
            sa[kq + 2][tok] = v.z;
            sa[kq + 3][tok] = v.w;
        }
        // stage W tile duplicated: 96 g x 16 k
#pragma unroll
        for (int q = 0; q < 12; q++) {
            int i = q * 128 + tid;
            int g = i >> 4;
            int k = i & 15;
            float wv = __ldg(&w_ih[g * GIN_ + k0 + k]);
            reinterpret_cast<ull*>(&sw[k][0])[g] = pack2(wv, wv);
        }
        __syncthreads();

#pragma unroll
        for (int k = 0; k < KT_; k++) {
            ulonglong2 av0 = *reinterpret_cast<const ulonglong2*>(&sa[k][tb]);
            ulonglong2 av1 = *reinterpret_cast<const ulonglong2*>(&sa[k][tb + 4]);
            const ulonglong2* wp = reinterpret_cast<const ulonglong2*>(&sw[k][0]) + gg * 3;
            ulonglong2 wv0 = wp[0];
            ulonglong2 wv1 = wp[1];
            ulonglong2 wv2 = wp[2];
            ull a0 = av0.x, a1 = av0.y, a2 = av1.x, a3 = av1.y;
            ull w0 = wv0.x, w1 = wv0.y, w2 = wv1.x, w3 = wv1.y, w4 = wv2.x, w5 = wv2.y;
            acc[0][0] = ffma2(a0, w0, acc[0][0]);
            acc[1][0] = ffma2(a1, w0, acc[1][0]);
            acc[2][0] = ffma2(a2, w0, acc[2][0]);
            acc[3][0] = ffma2(a3, w0, acc[3][0]);
            acc[0][1] = ffma2(a0, w1, acc[0][1]);
            acc[1][1] = ffma2(a1, w1, acc[1][1]);
            acc[2][1] = ffma2(a2, w1, acc[2][1]);
            acc[3][1] = ffma2(a3, w1, acc[3][1]);
            acc[0][2] = ffma2(a0, w2, acc[0][2]);
            acc[1][2] = ffma2(a1, w2, acc[1][2]);
            acc[2][2] = ffma2(a2, w2, acc[2][2]);
            acc[3][2] = ffma2(a3, w2, acc[3][2]);
            acc[0][3] = ffma2(a0, w3, acc[0][3]);
            acc[1][3] = ffma2(a1, w3, acc[1][3]);
            acc[2][3] = ffma2(a2, w3, acc[2][3]);
            acc[3][3] = ffma2(a3, w3, acc[3][3]);
            acc[0][4] = ffma2(a0, w4, acc[0][4]);
            acc[1][4] = ffma2(a1, w4, acc[1][4]);
            acc[2][4] = ffma2(a2, w4, acc[2][4]);
            acc[3][4] = ffma2(a3, w4, acc[3][4]);
            acc[0][5] = ffma2(a0, w5, acc[0][5]);
            acc[1][5] = ffma2(a1, w5, acc[1][5]);
            acc[2][5] = ffma2(a2, w5, acc[2][5]);
            acc[3][5] = ffma2(a3, w5, acc[3][5]);
        }
        __syncthreads();
    }

    // epilogue: 8 tokens x 6 g
#pragma unroll
    for (int p = 0; p < 4; p++) {
        int tok0 = base + tb + 2 * p;
        float lo[6], hi[6];
#pragma unroll
        for (int j = 0; j < 6; j++) {
            float2 v = unpack2(acc[p][j]);
            lo[j] = v.x + bias[j];
            hi[j] = v.y + bias[j];
        }
        float2* o0 = reinterpret_cast<float2*>(g_xp + (size_t)tok0 * G3_ + gbase);
        float2* o1 = reinterpret_cast<float2*>(g_xp + (size_t)(tok0 + 1) * G3_ + gbase);
        o0[0] = make_float2(lo[0], lo[1]);
        o0[1] = make_float2(lo[2], lo[3]);
        o0[2] = make_float2(lo[4], lo[5]);
        o1[0] = make_float2(hi[0], hi[1]);
        o1[1] = make_float2(hi[2], hi[3]);
        o1[2] = make_float2(hi[4], hi[5]);
    }
}

// =====================================================================
// Kernel 3: GRU scan. 1 warp per batch. lane l owns h[l].
// h broadcast via smem double-buffer; gate matvecs in f32x2.
// =====================================================================
__global__ void __launch_bounds__(32) k_gru(const float* __restrict__ w_hh,
                                            const float* __restrict__ b_hh)
{
    __shared__ __align__(16) float hb[2][GH_];
    int b = blockIdx.x;
    int l = threadIdx.x;

    // packed weight rows: lane l, gate rows as (k even, k odd) pairs
    ull wr2[16], wz2[16], wn2[16];
    const float2* wr = reinterpret_cast<const float2*>(w_hh + (0 * GH_ + l) * GH_);
    const float2* wz = reinterpret_cast<const float2*>(w_hh + (1 * GH_ + l) * GH_);
    const float2* wn = reinterpret_cast<const float2*>(w_hh + (2 * GH_ + l) * GH_);
#pragma unroll
    for (int k = 0; k < 16; k++) {
        float2 a = wr[k]; wr2[k] = pack2(a.x, a.y);
        float2 c = wz[k]; wz2[k] = pack2(c.x, c.y);
        float2 d = wn[k]; wn2[k] = pack2(d.x, d.y);
    }
    float br = b_hh[l], bz = b_hh[GH_ + l], bn = b_hh[2 * GH_ + l];

    float h = 0.0f;
    const float* xpb = g_xp + b * G3_;
    float* encb = g_enc + (size_t)b * H_ * GH_;

    float xr = xpb[l], xz = xpb[GH_ + l], xn = xpb[2 * GH_ + l];

    for (int t = 0; t < H_; t++) {
        float nxr = 0.f, nxz = 0.f, nxn = 0.f;
        if (t + 1 < H_) {
            const float* xt = xpb + (size_t)(t + 1) * (B_ * G3_);
            nxr = xt[l]; nxz = xt[GH_ + l]; nxn = xt[2 * GH_ + l];
        }

        hb[t & 1][l] = h;
        __syncwarp();
        const ull* hp = reinterpret_cast<const ull*>(&hb[t & 1][0]);

        ull ar0 = 0ull, ar1 = 0ull;
        ull az0 = 0ull, az1 = 0ull;
        ull an0 = 0ull, an1 = 0ull;
#pragma unroll
        for (int k = 0; k < 16; k += 2) {
            ull h0 = hp[k];
            ull h1 = hp[k + 1];
            ar0 = ffma2(h0, wr2[k], ar0);
            az0 = ffma2(h0, wz2[k], az0);
            an0 = ffma2(h0, wn2[k], an0);
            ar1 = ffma2(h1, wr2[k + 1], ar1);
            az1 = ffma2(h1, wz2[k + 1], az1);
            an1 = ffma2(h1, wn2[k + 1], an1);
        }
        float2 r0 = unpack2(ar0), r1 = unpack2(ar1);
        float2 z0 = unpack2(az0), z1 = unpack2(az1);
        float2 n0 = unpack2(an0), n1 = unpack2(an1);
        float ar = (r0.x + r0.y) + (r1.x + r1.y) + br;
        float az = (z0.x + z0.y) + (z1.x + z1.y) + bz;
        float an = (n0.x + n0.y) + (n1.x + n1.y) + bn;

        float rg = fsig(xr + ar);
        float zg = fsig(xz + az);
        float ng = ftanh(fmaf(rg, an, xn));
        h = fmaf(zg, h - ng, ng);

        encb[t * GH_ + l] = h;
        xr = nxr; xz = nxz; xn = nxn;
    }
}

// =====================================================================
// Kernel 4: attention scores, parallel over all (b,t)
// warp = (b, 32-t chunk); lane = g
// =====================================================================
__global__ void __launch_bounds__(128) k_scores(
    const float* __restrict__ w1, const float* __restrict__ b1,
    const float* __restrict__ w2, const float* __restrict__ b2)
{
    int wid   = (blockIdx.x * blockDim.x + threadIdx.x) >> 5;
    int lane  = threadIdx.x & 31;
    int b     = wid >> 4;       // 0..63
    int tch   = wid & 15;       // 0..15
    int tbeg  = tch * 32;

    const float* encb = g_enc + (size_t)b * H_ * GH_;
    float*       attb = g_att + (size_t)b * H_ * GH_;

    float w1r[GH_], w2r[GH_];
#pragma unroll
    for (int k = 0; k < GH_; k++) {
        w1r[k] = __ldg(&w1[lane * GH_ + k]);
        w2r[k] = __ldg(&w2[lane * GH_ + k]);
    }
    float b1l = __ldg(&b1[lane]), b2l = __ldg(&b2[lane]);

    int tend = min(tbeg + 32, H_);
    for (int t = tbeg; t < tend; t++) {
        float e = encb[t * GH_ + lane];
        float acch = b1l;
#pragma unroll
        for (int k = 0; k < GH_; k++)
            acch = fmaf(__shfl_sync(0xffffffffu, e, k), w1r[k], acch);
        float hid = ftanh(acch);
        float acca = b2l;
#pragma unroll
        for (int k = 0; k < GH_; k++)
            acca = fmaf(__shfl_sync(0xffffffffu, hid, k), w2r[k], acca);
        attb[t * GH_ + lane] = acca;
    }
}

// =====================================================================
// Kernel 5: softmax over t + pool + head. block per batch.
// =====================================================================
__global__ void __launch_bounds__(256) k_pool(
    const float* __restrict__ w3, const float* __restrict__ b3,
    float* __restrict__ out)
{
    int b    = blockIdx.x;
    int tid  = threadIdx.x;
    int g    = tid & 31;
    int part = tid >> 5;

    const float* encb = g_enc + (size_t)b * H_ * GH_;
    const float* attb = g_att + (size_t)b * H_ * GH_;

    __shared__ float redm[8][GH_];
    __shared__ float reds[8][GH_];
    __shared__ float redp[8][GH_];
    __shared__ float pooled[GH_];

    float m = -1e30f;
    for (int t = part; t < H_; t += 8)
        m = fmaxf(m, attb[t * GH_ + g]);
    redm[part][g] = m;
    __syncthreads();
    float mg = redm[0][g];
#pragma unroll
    for (int p = 1; p < 8; p++) mg = fmaxf(mg, redm[p][g]);

    float se = 0.0f, pw = 0.0f;
    for (int t = part; t < H_; t += 8) {
        float ex = __expf(attb[t * GH_ + g] - mg);
        se += ex;
        pw = fmaf(ex, encb[t * GH_ + g], pw);
    }
    reds[part][g] = se;
    redp[part][g] = pw;
    __syncthreads();
    if (part == 0) {
        float ts = 0.0f, tp = 0.0f;
#pragma unroll
        for (int p = 0; p < 8; p++) { ts += reds[p][g]; tp += redp[p][g]; }
        pooled[g] = tp / ts;
    }
    __syncthreads();

    if (tid < 64) {
        int o  = tid >> 5;
        int gg = tid & 31;
        float v = pooled[gg] * __ldg(&w3[o * GH_ + gg]);
#pragma unroll
        for (int s = 16; s > 0; s >>= 1)
            v += __shfl_xor_sync(0xffffffffu, v, s);
        if (gg == 0)
            out[b * 2 + o] = v + __ldg(&b3[o]);
    }
}

// =====================================================================
extern "C" void kernel_launch(void* const* d_in, const int* in_sizes, int n_in,
                              void* d_out, int out_size)
{
    const float* x     = (const float*)d_in[0];
    const float* p_w   = (const float*)d_in[1];
    const float* p_b   = (const float*)d_in[2];
    const float* dcn_w = (const float*)d_in[3];
    const float* dcn_b = (const float*)d_in[4];
    const float* w_ih  = (const float*)d_in[5];
    const float* w_hh  = (const float*)d_in[6];
    const float* b_ih  = (const float*)d_in[7];
    const float* b_hh  = (const float*)d_in[8];
    const float* w1    = (const float*)d_in[9];
    const float* b1    = (const float*)d_in[10];
    const float* w2    = (const float*)d_in[11];
    const float* b2    = (const float*)d_in[12];
    const float* w3    = (const float*)d_in[13];
    const float* b3    = (const float*)d_in[14];
    float* out = (float*)d_out;

    {
        int total   = B_ * H_ * WO_;
        int threads = 128;
        int blocks  = (total + threads - 1) / threads;
        k_deform<<<blocks, threads>>>(x, p_w, p_b, dcn_w, dcn_b);
    }
    {
        k_gemm<<<NTOK_ / TM_, 128>>>(w_ih, b_ih);   // 510 blocks
    }
    {
        k_gru<<<B_, GH_>>>(w_hh, b_hh);
    }
    {
        k_scores<<<256, 128>>>(w1, b1, w2, b2);     // 1024 warps
    }
    {
        k_pool<<<B_, 256>>>(w3, b3, out);
    }
}

// round 3
// speedup vs baseline: 2.2703x; 1.5552x over previous
#include <cuda_runtime.h>
#include <cuda_bf16.h>
#include <math.h>

// ---------------- problem constants ----------------
#define B_      64
#define T_      512
#define WIN_    40
#define KS_     3
#define NPT_    9          // KS*KS
#define CF_     8
#define H_      510        // T - 2
#define WO_     38         // WIN - 2
#define GIN_    304        // WO_*CF_
#define GH_     32
#define G3_     96         // 3*GH
#define NTOK_   (H_ * B_)  // 32640

typedef unsigned long long ull;

// ---------------- scratch (device globals; no cudaMalloc allowed) -------------
__device__ float g_seq[NTOK_ * GIN_];   // (t,b,f)  f = w*8 + c
__device__ float g_xp [NTOK_ * G3_];    // (b,t,g)  <-- batch-major for GRU streaming
__device__ float g_enc[B_ * H_ * GH_];  // (b,t,g)
__device__ float g_att[B_ * H_ * GH_];  // (b,t,g)

// ---------------- f32x2 packed math helpers ----------------
__device__ __forceinline__ ull ffma2(ull a, ull b, ull c) {
    ull d;
    asm("fma.rn.f32x2 %0, %1, %2, %3;" : "=l"(d) : "l"(a), "l"(b), "l"(c));
    return d;
}
__device__ __forceinline__ ull pack2(float x, float y) {
    ull v;
    asm("mov.b64 %0, {%1, %2};" : "=l"(v) : "f"(x), "f"(y));
    return v;
}
__device__ __forceinline__ float2 unpack2(ull v) {
    float2 r;
    asm("mov.b64 {%0, %1}, %2;" : "=f"(r.x), "=f"(r.y) : "l"(v));
    return r;
}

// ---------------- fast activations (ex2/rcp approx) ----------------
#define LOG2E_ 1.4426950408889634f
__device__ __forceinline__ float ex2a(float x) {
    float r; asm("ex2.approx.f32 %0, %1;" : "=f"(r) : "f"(x)); return r;
}
__device__ __forceinline__ float rcpa(float x) {
    float r; asm("rcp.approx.f32 %0, %1;" : "=f"(r) : "f"(x)); return r;
}
__device__ __forceinline__ float fsig(float x) {
    return rcpa(1.0f + ex2a(-LOG2E_ * x));
}
__device__ __forceinline__ float ftanh(float x) {
    return fmaf(2.0f, rcpa(1.0f + ex2a(-2.0f * LOG2E_ * x)), -1.0f);
}

// =====================================================================
// Kernel 1: deformable conv -> g_seq (t,b, w*8+c)
// =====================================================================
__global__ void k_deform(const float* __restrict__ x,
                         const float* __restrict__ p_w,
                         const float* __restrict__ p_b,
                         const float* __restrict__ dcn_w,
                         const float* __restrict__ dcn_b)
{
    __shared__ float s_pw[2 * NPT_ * NPT_];
    __shared__ float s_pb[2 * NPT_];
    __shared__ float s_dw[CF_ * NPT_];
    __shared__ float s_db[CF_];

    int tid = threadIdx.x;
    for (int i = tid; i < 2 * NPT_ * NPT_; i += blockDim.x) s_pw[i] = p_w[i];
    for (int i = tid; i < 2 * NPT_;       i += blockDim.x) s_pb[i] = p_b[i];
    for (int i = tid; i < CF_ * NPT_;     i += blockDim.x) s_dw[i] = dcn_w[i];
    for (int i = tid; i < CF_;            i += blockDim.x) s_db[i] = dcn_b[i];
    __syncthreads();

    int idx = blockIdx.x * blockDim.x + tid;
    const int total = B_ * H_ * WO_;
    if (idx >= total) return;

    int w  = idx % WO_;
    int b  = (idx / WO_) % B_;
    int t  = idx / (WO_ * B_);

    const float* xb = x + b * (T_ * WIN_);

    float patch[NPT_];
#pragma unroll
    for (int ky = 0; ky < KS_; ky++)
#pragma unroll
        for (int kx = 0; kx < KS_; kx++)
            patch[ky * KS_ + kx] = xb[(t + ky) * WIN_ + (w + kx)];

    float off[2 * NPT_];
#pragma unroll
    for (int o = 0; o < 2 * NPT_; o++) off[o] = s_pb[o];
#pragma unroll
    for (int k = 0; k < NPT_; k++) {
        float pv = patch[k];
#pragma unroll
        for (int o = 0; o < 2 * NPT_; o++)
            off[o] = fmaf(pv, s_pw[o * NPT_ + k], off[o]);
    }

    float acc[CF_];
#pragma unroll
    for (int c = 0; c < CF_; c++) acc[c] = s_db[c];

#pragma unroll
    for (int n = 0; n < NPT_; n++) {
        float py = off[n]        + (float)(n / 3 - 1) + (float)(t + 1);
        float px = off[NPT_ + n] + (float)(n % 3 - 1) + (float)(w + 1);
        py = fminf(fmaxf(py, 0.0f), (float)(T_ - 1));
        px = fminf(fmaxf(px, 0.0f), (float)(WIN_ - 1));
        int y0 = (int)floorf(py);
        int x0 = (int)floorf(px);
        int y1 = min(y0 + 1, T_ - 1);
        int x1 = min(x0 + 1, WIN_ - 1);
        float wy = py - (float)y0;
        float wx = px - (float)x0;
        float g00 = __ldg(&xb[y0 * WIN_ + x0]);
        float g01 = __ldg(&xb[y0 * WIN_ + x1]);
        float g10 = __ldg(&xb[y1 * WIN_ + x0]);
        float g11 = __ldg(&xb[y1 * WIN_ + x1]);
        float top = g00 + wx * (g01 - g00);
        float bot = g10 + wx * (g11 - g10);
        float s   = top + wy * (bot - top);
#pragma unroll
        for (int c = 0; c < CF_; c++)
            acc[c] = fmaf(s, s_dw[c * NPT_ + n], acc[c]);
    }

    float* dst = g_seq + (size_t)(t * B_ + b) * GIN_ + w * CF_;
    *reinterpret_cast<float4*>(dst)     = make_float4(acc[0], acc[1], acc[2], acc[3]);
    *reinterpret_cast<float4*>(dst + 4) = make_float4(acc[4], acc[5], acc[6], acc[7]);
}

// =====================================================================
// Kernel 2: GEMM 32640x96x304 with fma.rn.f32x2, conflict-free smem
// block: 64 tokens x 96 g, 128 threads; thread: 8 tokens x 6 g
// output layout: g_xp (b,t,g)
// =====================================================================
#define TM_ 64
#define KT_ 16
#define SA_W (TM_ + 2)        // 66 floats/row: conflict-free transpose stores
#define SW_W (2 * G3_ + 2)    // 194 floats/row: conflict-free dup-w stores
__global__ void __launch_bounds__(128) k_gemm(const float* __restrict__ w_ih,
                                              const float* __restrict__ b_ih)
{
    __shared__ __align__(16) float sa[KT_][SA_W];
    __shared__ __align__(16) float sw[KT_][SW_W];

    int tid = threadIdx.x;
    int tg  = tid >> 4;          // 0..7
    int gg  = tid & 15;          // 0..15
    int tb  = tg * 8;
    int gbase = gg * 6;
    int base = blockIdx.x * TM_;

    float bias[6];
#pragma unroll
    for (int j = 0; j < 6; j++) bias[j] = __ldg(&b_ih[gbase + j]);

    ull acc[4][6];
#pragma unroll
    for (int p = 0; p < 4; p++)
#pragma unroll
        for (int j = 0; j < 6; j++) acc[p][j] = 0ull;

    for (int kt = 0; kt < GIN_ / KT_; kt++) {
        int k0 = kt * KT_;
#pragma unroll
        for (int q = 0; q < 2; q++) {
            int i   = q * 128 + tid;
            int tok = i >> 2;
            int kq  = (i & 3) * 4;
            float4 v = *reinterpret_cast<const float4*>(
                g_seq + (size_t)(base + tok) * GIN_ + k0 + kq);
            sa[kq + 0][tok] = v.x;
            sa[kq + 1][tok] = v.y;
            sa[kq + 2][tok] = v.z;
            sa[kq + 3][tok] = v.w;
        }
#pragma unroll
        for (int q = 0; q < 12; q++) {
            int i = q * 128 + tid;
            int g = i >> 4;
            int k = i & 15;
            float wv = __ldg(&w_ih[g * GIN_ + k0 + k]);
            *reinterpret_cast<ull*>(&sw[k][2 * g]) = pack2(wv, wv);
        }
        __syncthreads();

#pragma unroll
        for (int k = 0; k < KT_; k++) {
            const ull* ap = reinterpret_cast<const ull*>(&sa[k][tb]);
            ull a0 = ap[0], a1 = ap[1], a2 = ap[2], a3 = ap[3];
            const ull* wp = reinterpret_cast<const ull*>(&sw[k][2 * gbase]);
            ull w0 = wp[0], w1 = wp[1], w2 = wp[2], w3 = wp[3], w4 = wp[4], w5 = wp[5];
            acc[0][0] = ffma2(a0, w0, acc[0][0]);
            acc[1][0] = ffma2(a1, w0, acc[1][0]);
            acc[2][0] = ffma2(a2, w0, acc[2][0]);
            acc[3][0] = ffma2(a3, w0, acc[3][0]);
            acc[0][1] = ffma2(a0, w1, acc[0][1]);
            acc[1][1] = ffma2(a1, w1, acc[1][1]);
            acc[2][1] = ffma2(a2, w1, acc[2][1]);
            acc[3][1] = ffma2(a3, w1, acc[3][1]);
            acc[0][2] = ffma2(a0, w2, acc[0][2]);
            acc[1][2] = ffma2(a1, w2, acc[1][2]);
            acc[2][2] = ffma2(a2, w2, acc[2][2]);
            acc[3][2] = ffma2(a3, w2, acc[3][2]);
            acc[0][3] = ffma2(a0, w3, acc[0][3]);
            acc[1][3] = ffma2(a1, w3, acc[1][3]);
            acc[2][3] = ffma2(a2, w3, acc[2][3]);
            acc[3][3] = ffma2(a3, w3, acc[3][3]);
            acc[0][4] = ffma2(a0, w4, acc[0][4]);
            acc[1][4] = ffma2(a1, w4, acc[1][4]);
            acc[2][4] = ffma2(a2, w4, acc[2][4]);
            acc[3][4] = ffma2(a3, w4, acc[3][4]);
            acc[0][5] = ffma2(a0, w5, acc[0][5]);
            acc[1][5] = ffma2(a1, w5, acc[1][5]);
            acc[2][5] = ffma2(a2, w5, acc[2][5]);
            acc[3][5] = ffma2(a3, w5, acc[3][5]);
        }
        __syncthreads();
    }

    // epilogue: 8 tokens x 6 g -> g_xp (b,t,g)
#pragma unroll
    for (int p = 0; p < 4; p++) {
        int tok0 = base + tb + 2 * p;
        float lo[6], hi[6];
#pragma unroll
        for (int j = 0; j < 6; j++) {
            float2 v = unpack2(acc[p][j]);
            lo[j] = v.x + bias[j];
            hi[j] = v.y + bias[j];
        }
        int b0 = tok0 & (B_ - 1), t0 = tok0 >> 6;
        int b1v = (tok0 + 1) & (B_ - 1), t1v = (tok0 + 1) >> 6;
        float2* o0 = reinterpret_cast<float2*>(g_xp + ((size_t)b0 * H_ + t0) * G3_ + gbase);
        float2* o1 = reinterpret_cast<float2*>(g_xp + ((size_t)b1v * H_ + t1v) * G3_ + gbase);
        o0[0] = make_float2(lo[0], lo[1]);
        o0[1] = make_float2(lo[2], lo[3]);
        o0[2] = make_float2(lo[4], lo[5]);
        o1[0] = make_float2(hi[0], hi[1]);
        o1[1] = make_float2(hi[2], hi[3]);
        o1[2] = make_float2(hi[4], hi[5]);
    }
}

// =====================================================================
// Kernel 3: GRU scan. 1 warp per batch. lane l owns h[l].
// xp is (b,t,g): contiguous streaming; depth-2 prefetch; fast activations.
// =====================================================================
__global__ void __launch_bounds__(32) k_gru(const float* __restrict__ w_hh,
                                            const float* __restrict__ b_hh)
{
    __shared__ __align__(16) float hb[2][GH_];
    int b = blockIdx.x;
    int l = threadIdx.x;

    ull wr2[16], wz2[16], wn2[16];
    const float2* wr = reinterpret_cast<const float2*>(w_hh + (0 * GH_ + l) * GH_);
    const float2* wz = reinterpret_cast<const float2*>(w_hh + (1 * GH_ + l) * GH_);
    const float2* wn = reinterpret_cast<const float2*>(w_hh + (2 * GH_ + l) * GH_);
#pragma unroll
    for (int k = 0; k < 16; k++) {
        float2 a = wr[k]; wr2[k] = pack2(a.x, a.y);
        float2 c = wz[k]; wz2[k] = pack2(c.x, c.y);
        float2 d = wn[k]; wn2[k] = pack2(d.x, d.y);
    }
    float br = b_hh[l], bz = b_hh[GH_ + l], bn = b_hh[2 * GH_ + l];

    float h = 0.0f;
    const float* xpb = g_xp + (size_t)b * H_ * G3_;
    float* encb = g_enc + (size_t)b * H_ * GH_;

    // depth-2 prefetch
    float xr0 = xpb[l],        xz0 = xpb[GH_ + l],        xn0 = xpb[2 * GH_ + l];
    float xr1 = xpb[G3_ + l],  xz1 = xpb[G3_ + GH_ + l],  xn1 = xpb[G3_ + 2 * GH_ + l];

    for (int t = 0; t < H_; t++) {
        float xr2 = 0.f, xz2 = 0.f, xn2 = 0.f;
        if (t + 2 < H_) {
            const float* row = xpb + (size_t)(t + 2) * G3_;
            xr2 = row[l]; xz2 = row[GH_ + l]; xn2 = row[2 * GH_ + l];
        }

        hb[t & 1][l] = h;
        __syncwarp();
        const ulonglong2* hp = reinterpret_cast<const ulonglong2*>(&hb[t & 1][0]);

        ull ar0 = 0ull, ar1 = 0ull;
        ull az0 = 0ull, az1 = 0ull;
        ull an0 = 0ull, an1 = 0ull;
#pragma unroll
        for (int kk = 0; kk < 8; kk++) {
            ulonglong2 hv = hp[kk];
            ull h0 = hv.x, h1 = hv.y;
            ar0 = ffma2(h0, wr2[2 * kk], ar0);
            az0 = ffma2(h0, wz2[2 * kk], az0);
            an0 = ffma2(h0, wn2[2 * kk], an0);
            ar1 = ffma2(h1, wr2[2 * kk + 1], ar1);
            az1 = ffma2(h1, wz2[2 * kk + 1], az1);
            an1 = ffma2(h1, wn2[2 * kk + 1], an1);
        }
        float2 r0 = unpack2(ar0), r1 = unpack2(ar1);
        float2 z0 = unpack2(az0), z1 = unpack2(az1);
        float2 n0 = unpack2(an0), n1 = unpack2(an1);
        float ar = (r0.x + r0.y) + (r1.x + r1.y) + br;
        float az = (z0.x + z0.y) + (z1.x + z1.y) + bz;
        float an = (n0.x + n0.y) + (n1.x + n1.y) + bn;

        float rg = fsig(xr0 + ar);
        float zg = fsig(xz0 + az);
        float ng = ftanh(fmaf(rg, an, xn0));
        h = fmaf(zg, h - ng, ng);

        encb[t * GH_ + l] = h;
        xr0 = xr1; xz0 = xz1; xn0 = xn1;
        xr1 = xr2; xz1 = xz2; xn1 = xn2;
    }
}

// =====================================================================
// Kernel 4: attention scores — one thread per token, GEMM-style, f32x2
// =====================================================================
__global__ void __launch_bounds__(128) k_scores(
    const float* __restrict__ w1, const float* __restrict__ b1,
    const float* __restrict__ w2, const float* __restrict__ b2)
{
    __shared__ __align__(16) float sw1[GH_ * GH_];
    __shared__ __align__(16) float sw2[GH_ * GH_];
    __shared__ float sb1[GH_], sb2[GH_];

    int tid = threadIdx.x;
#pragma unroll
    for (int q = 0; q < 8; q++) {
        sw1[q * 128 + tid] = w1[q * 128 + tid];
        sw2[q * 128 + tid] = w2[q * 128 + tid];
    }
    if (tid < GH_) { sb1[tid] = b1[tid]; sb2[tid] = b2[tid]; }
    __syncthreads();

    int tok = blockIdx.x * 128 + tid;   // 0..NTOK-1, grid covers exactly
    const float* erow = g_enc + (size_t)tok * GH_;

    // load enc row as 16 f32x2 pairs
    ull e2[16];
#pragma unroll
    for (int i = 0; i < 8; i++) {
        ulonglong2 v = reinterpret_cast<const ulonglong2*>(erow)[i];
        e2[2 * i] = v.x; e2[2 * i + 1] = v.y;
    }

    const ull* w1p = reinterpret_cast<const ull*>(sw1);
    const ull* w2p = reinterpret_cast<const ull*>(sw2);

    // layer 1: hid_j = tanh(e . w1[j] + b1[j])
    ull h2[16];
#pragma unroll 4
    for (int j = 0; j < GH_; j += 2) {
        ull a = 0ull, bqq = 0ull;
#pragma unroll
        for (int k = 0; k < 16; k++) {
            a   = ffma2(e2[k], w1p[j * 16 + k], a);
            bqq = ffma2(e2[k], w1p[(j + 1) * 16 + k], bqq);
        }
        float2 fa = unpack2(a), fb = unpack2(bqq);
        float ha = ftanh(fa.x + fa.y + sb1[j]);
        float hbv = ftanh(fb.x + fb.y + sb1[j + 1]);
        h2[j >> 1] = pack2(ha, hbv);
    }

    // layer 2: att_g = hid . w2[g] + b2[g]
    float outv[GH_];
#pragma unroll 4
    for (int g = 0; g < GH_; g += 2) {
        ull a = 0ull, bqq = 0ull;
#pragma unroll
        for (int k = 0; k < 16; k++) {
            a   = ffma2(h2[k], w2p[g * 16 + k], a);
            bqq = ffma2(h2[k], w2p[(g + 1) * 16 + k], bqq);
        }
        float2 fa = unpack2(a), fb = unpack2(bqq);
        outv[g]     = fa.x + fa.y + sb2[g];
        outv[g + 1] = fb.x + fb.y + sb2[g + 1];
    }

    float* arow = g_att + (size_t)tok * GH_;
#pragma unroll
    for (int i = 0; i < 8; i++)
        reinterpret_cast<float4*>(arow)[i] =
            make_float4(outv[4 * i], outv[4 * i + 1], outv[4 * i + 2], outv[4 * i + 3]);
}

// =====================================================================
// Kernel 5: softmax over t + pool + head. block per batch, 512 threads.
// NOTE: g_att here is indexed (b,t,g) — same as tok = b*H+t ordering used
// by k_scores only if tok was (b*H+t). k_scores uses tok = linear over
// g_enc which IS (b,t,g). Consistent.
// =====================================================================
#define PPARTS 16
__global__ void __launch_bounds__(512) k_pool(
    const float* __restrict__ w3, const float* __restrict__ b3,
    float* __restrict__ out)
{
    int b    = blockIdx.x;
    int tid  = threadIdx.x;
    int g    = tid & 31;
    int part = tid >> 5;

    const float* encb = g_enc + (size_t)b * H_ * GH_;
    const float* attb = g_att + (size_t)b * H_ * GH_;

    __shared__ float redm[PPARTS][GH_];
    __shared__ float reds[PPARTS][GH_];
    __shared__ float redp[PPARTS][GH_];
    __shared__ float pooled[GH_];

    float m = -1e30f;
    for (int t = part; t < H_; t += PPARTS)
        m = fmaxf(m, attb[t * GH_ + g]);
    redm[part][g] = m;
    __syncthreads();
    float mg = redm[0][g];
#pragma unroll
    for (int p = 1; p < PPARTS; p++) mg = fmaxf(mg, redm[p][g]);

    float se = 0.0f, pw = 0.0f;
    for (int t = part; t < H_; t += PPARTS) {
        float ex = __expf(attb[t * GH_ + g] - mg);
        se += ex;
        pw = fmaf(ex, encb[t * GH_ + g], pw);
    }
    reds[part][g] = se;
    redp[part][g] = pw;
    __syncthreads();
    if (part == 0) {
        float ts = 0.0f, tp = 0.0f;
#pragma unroll
        for (int p = 0; p < PPARTS; p++) { ts += reds[p][g]; tp += redp[p][g]; }
        pooled[g] = tp / ts;
    }
    __syncthreads();

    if (tid < 64) {
        int o  = tid >> 5;
        int gg = tid & 31;
        float v = pooled[gg] * __ldg(&w3[o * GH_ + gg]);
#pragma unroll
        for (int s = 16; s > 0; s >>= 1)
            v += __shfl_xor_sync(0xffffffffu, v, s);
        if (gg == 0)
            out[b * 2 + o] = v + __ldg(&b3[o]);
    }
}

// =====================================================================
extern "C" void kernel_launch(void* const* d_in, const int* in_sizes, int n_in,
                              void* d_out, int out_size)
{
    const float* x     = (const float*)d_in[0];
    const float* p_w   = (const float*)d_in[1];
    const float* p_b   = (const float*)d_in[2];
    const float* dcn_w = (const float*)d_in[3];
    const float* dcn_b = (const float*)d_in[4];
    const float* w_ih  = (const float*)d_in[5];
    const float* w_hh  = (const float*)d_in[6];
    const float* b_ih  = (const float*)d_in[7];
    const float* b_hh  = (const float*)d_in[8];
    const float* w1    = (const float*)d_in[9];
    const float* b1    = (const float*)d_in[10];
    const float* w2    = (const float*)d_in[11];
    const float* b2    = (const float*)d_in[12];
    const float* w3    = (const float*)d_in[13];
    const float* b3    = (const float*)d_in[14];
    float* out = (float*)d_out;

    {
        int total   = B_ * H_ * WO_;
        int threads = 128;
        int blocks  = (total + threads - 1) / threads;
        k_deform<<<blocks, threads>>>(x, p_w, p_b, dcn_w, dcn_b);
    }
    {
        k_gemm<<<NTOK_ / TM_, 128>>>(w_ih, b_ih);   // 510 blocks
    }
    {
        k_gru<<<B_, GH_>>>(w_hh, b_hh);
    }
    {
        k_scores<<<NTOK_ / 128, 128>>>(w1, b1, w2, b2);  // 255 blocks
    }
    {
        k_pool<<<B_, 512>>>(w3, b3, out);
    }
}

// round 4
// speedup vs baseline: 2.6318x; 1.1592x over previous
#include <cuda_runtime.h>
#include <cuda_bf16.h>
#include <math.h>

// ---------------- problem constants ----------------
#define B_      64
#define T_      512
#define WIN_    40
#define KS_     3
#define NPT_    9          // KS*KS
#define CF_     8
#define H_      510        // T - 2
#define WO_     38         // WIN - 2
#define GIN_    304        // WO_*CF_
#define GH_     32
#define G3_     96         // 3*GH
#define NTOK_   (H_ * B_)  // 32640

typedef unsigned long long ull;

// ---------------- scratch (device globals; no cudaMalloc allowed) -------------
__device__ float g_seq[NTOK_ * GIN_];   // (t,b,f)
__device__ float g_xp [NTOK_ * G3_];    // (b,t,g)
__device__ float g_enc[B_ * H_ * GH_];  // (b,t,g)
__device__ float g_att[B_ * H_ * GH_];  // (b,t,g)

// ---------------- f32x2 packed math helpers ----------------
__device__ __forceinline__ ull ffma2(ull a, ull b, ull c) {
    ull d;
    asm("fma.rn.f32x2 %0, %1, %2, %3;" : "=l"(d) : "l"(a), "l"(b), "l"(c));
    return d;
}
__device__ __forceinline__ ull fadd2(ull a, ull b) {
    ull d;
    asm("add.rn.f32x2 %0, %1, %2;" : "=l"(d) : "l"(a), "l"(b));
    return d;
}
__device__ __forceinline__ ull pack2(float x, float y) {
    ull v;
    asm("mov.b64 %0, {%1, %2};" : "=l"(v) : "f"(x), "f"(y));
    return v;
}
__device__ __forceinline__ float2 unpack2(ull v) {
    float2 r;
    asm("mov.b64 {%0, %1}, %2;" : "=f"(r.x), "=f"(r.y) : "l"(v));
    return r;
}

// ---------------- fast activations via tanh.approx (single MUFU) -------------
__device__ __forceinline__ float tanha(float x) {
    float r; asm("tanh.approx.f32 %0, %1;" : "=f"(r) : "f"(x)); return r;
}
__device__ __forceinline__ float fsig(float x) {
    return fmaf(0.5f, tanha(0.5f * x), 0.5f);
}

// =====================================================================
// Kernel 1: deformable conv -> g_seq (t,b, w*8+c)
// =====================================================================
__global__ void k_deform(const float* __restrict__ x,
                         const float* __restrict__ p_w,
                         const float* __restrict__ p_b,
                         const float* __restrict__ dcn_w,
                         const float* __restrict__ dcn_b)
{
    __shared__ float s_pw[2 * NPT_ * NPT_];
    __shared__ float s_pb[2 * NPT_];
    __shared__ float s_dw[CF_ * NPT_];
    __shared__ float s_db[CF_];

    int tid = threadIdx.x;
    for (int i = tid; i < 2 * NPT_ * NPT_; i += blockDim.x) s_pw[i] = p_w[i];
    for (int i = tid; i < 2 * NPT_;       i += blockDim.x) s_pb[i] = p_b[i];
    for (int i = tid; i < CF_ * NPT_;     i += blockDim.x) s_dw[i] = dcn_w[i];
    for (int i = tid; i < CF_;            i += blockDim.x) s_db[i] = dcn_b[i];
    __syncthreads();

    int idx = blockIdx.x * blockDim.x + tid;
    const int total = B_ * H_ * WO_;
    if (idx >= total) return;

    int w  = idx % WO_;
    int b  = (idx / WO_) % B_;
    int t  = idx / (WO_ * B_);

    const float* xb = x + b * (T_ * WIN_);

    float patch[NPT_];
#pragma unroll
    for (int ky = 0; ky < KS_; ky++)
#pragma unroll
        for (int kx = 0; kx < KS_; kx++)
            patch[ky * KS_ + kx] = xb[(t + ky) * WIN_ + (w + kx)];

    float off[2 * NPT_];
#pragma unroll
    for (int o = 0; o < 2 * NPT_; o++) off[o] = s_pb[o];
#pragma unroll
    for (int k = 0; k < NPT_; k++) {
        float pv = patch[k];
#pragma unroll
        for (int o = 0; o < 2 * NPT_; o++)
            off[o] = fmaf(pv, s_pw[o * NPT_ + k], off[o]);
    }

    float acc[CF_];
#pragma unroll
    for (int c = 0; c < CF_; c++) acc[c] = s_db[c];

#pragma unroll
    for (int n = 0; n < NPT_; n++) {
        float py = off[n]        + (float)(n / 3 - 1) + (float)(t + 1);
        float px = off[NPT_ + n] + (float)(n % 3 - 1) + (float)(w + 1);
        py = fminf(fmaxf(py, 0.0f), (float)(T_ - 1));
        px = fminf(fmaxf(px, 0.0f), (float)(WIN_ - 1));
        int y0 = (int)floorf(py);
        int x0 = (int)floorf(px);
        int y1 = min(y0 + 1, T_ - 1);
        int x1 = min(x0 + 1, WIN_ - 1);
        float wy = py - (float)y0;
        float wx = px - (float)x0;
        float g00 = __ldg(&xb[y0 * WIN_ + x0]);
        float g01 = __ldg(&xb[y0 * WIN_ + x1]);
        float g10 = __ldg(&xb[y1 * WIN_ + x0]);
        float g11 = __ldg(&xb[y1 * WIN_ + x1]);
        float top = g00 + wx * (g01 - g00);
        float bot = g10 + wx * (g11 - g10);
        float s   = top + wy * (bot - top);
#pragma unroll
        for (int c = 0; c < CF_; c++)
            acc[c] = fmaf(s, s_dw[c * NPT_ + n], acc[c]);
    }

    float* dst = g_seq + (size_t)(t * B_ + b) * GIN_ + w * CF_;
    *reinterpret_cast<float4*>(dst)     = make_float4(acc[0], acc[1], acc[2], acc[3]);
    *reinterpret_cast<float4*>(dst + 4) = make_float4(acc[4], acc[5], acc[6], acc[7]);
}

// =====================================================================
// Kernel 2: GEMM 32640x96x304, fma.rn.f32x2, double-buffered smem
// block: 64 tokens x 96 g, 128 threads; thread: 8 tokens x 6 g
// =====================================================================
#define TM_ 64
#define KT_ 16
#define NKT_ (GIN_ / KT_)     // 19
#define SA_W (TM_ + 2)        // 66
#define SW_W (2 * G3_ + 2)    // 194
__global__ void __launch_bounds__(128) k_gemm(const float* __restrict__ w_ih,
                                              const float* __restrict__ b_ih)
{
    __shared__ __align__(16) float sa[2][KT_][SA_W];
    __shared__ __align__(16) float sw[2][KT_][SW_W];

    int tid = threadIdx.x;
    int tg  = tid >> 4;
    int gg  = tid & 15;
    int tb  = tg * 8;
    int gbase = gg * 6;
    int base = blockIdx.x * TM_;

    // staging index precompute
    int s_tok0 = tid >> 2;           // q=0 token
    int s_kq   = (tid & 3) * 4;
    int s_g    = tid >> 4;           // q block adds 8 each
    int s_k    = tid & 15;

    float bias[6];
#pragma unroll
    for (int j = 0; j < 6; j++) bias[j] = __ldg(&b_ih[gbase + j]);

    ull acc[4][6];
#pragma unroll
    for (int p = 0; p < 4; p++)
#pragma unroll
        for (int j = 0; j < 6; j++) acc[p][j] = 0ull;

    float4 pa[2];
    float  pw[12];

    // prologue: load tile 0
    {
#pragma unroll
        for (int q = 0; q < 2; q++)
            pa[q] = *reinterpret_cast<const float4*>(
                g_seq + (size_t)(base + s_tok0 + q * 32) * GIN_ + s_kq);
#pragma unroll
        for (int q = 0; q < 12; q++)
            pw[q] = __ldg(&w_ih[(s_g + q * 8) * GIN_ + s_k]);
    }
    // store tile 0 into buffer 0
    {
#pragma unroll
        for (int q = 0; q < 2; q++) {
            int tok = s_tok0 + q * 32;
            sa[0][s_kq + 0][tok] = pa[q].x;
            sa[0][s_kq + 1][tok] = pa[q].y;
            sa[0][s_kq + 2][tok] = pa[q].z;
            sa[0][s_kq + 3][tok] = pa[q].w;
        }
#pragma unroll
        for (int q = 0; q < 12; q++)
            *reinterpret_cast<ull*>(&sw[0][s_k][2 * (s_g + q * 8)]) = pack2(pw[q], pw[q]);
    }
    __syncthreads();

    for (int kt = 0; kt < NKT_; kt++) {
        int cur = kt & 1;
        // prefetch next tile into registers
        if (kt + 1 < NKT_) {
            int k0 = (kt + 1) * KT_;
#pragma unroll
            for (int q = 0; q < 2; q++)
                pa[q] = *reinterpret_cast<const float4*>(
                    g_seq + (size_t)(base + s_tok0 + q * 32) * GIN_ + k0 + s_kq);
#pragma unroll
            for (int q = 0; q < 12; q++)
                pw[q] = __ldg(&w_ih[(s_g + q * 8) * GIN_ + k0 + s_k]);
        }

        // compute current tile
#pragma unroll
        for (int k = 0; k < KT_; k++) {
            const ull* ap = reinterpret_cast<const ull*>(&sa[cur][k][tb]);
            ull a0 = ap[0], a1 = ap[1], a2 = ap[2], a3 = ap[3];
            const ull* wp = reinterpret_cast<const ull*>(&sw[cur][k][2 * gbase]);
            ull w0 = wp[0], w1 = wp[1], w2 = wp[2], w3 = wp[3], w4 = wp[4], w5 = wp[5];
            acc[0][0] = ffma2(a0, w0, acc[0][0]);
            acc[1][0] = ffma2(a1, w0, acc[1][0]);
            acc[2][0] = ffma2(a2, w0, acc[2][0]);
            acc[3][0] = ffma2(a3, w0, acc[3][0]);
            acc[0][1] = ffma2(a0, w1, acc[0][1]);
            acc[1][1] = ffma2(a1, w1, acc[1][1]);
            acc[2][1] = ffma2(a2, w1, acc[2][1]);
            acc[3][1] = ffma2(a3, w1, acc[3][1]);
            acc[0][2] = ffma2(a0, w2, acc[0][2]);
            acc[1][2] = ffma2(a1, w2, acc[1][2]);
            acc[2][2] = ffma2(a2, w2, acc[2][2]);
            acc[3][2] = ffma2(a3, w2, acc[3][2]);
            acc[0][3] = ffma2(a0, w3, acc[0][3]);
            acc[1][3] = ffma2(a1, w3, acc[1][3]);
            acc[2][3] = ffma2(a2, w3, acc[2][3]);
            acc[3][3] = ffma2(a3, w3, acc[3][3]);
            acc[0][4] = ffma2(a0, w4, acc[0][4]);
            acc[1][4] = ffma2(a1, w4, acc[1][4]);
            acc[2][4] = ffma2(a2, w4, acc[2][4]);
            acc[3][4] = ffma2(a3, w4, acc[3][4]);
            acc[0][5] = ffma2(a0, w5, acc[0][5]);
            acc[1][5] = ffma2(a1, w5, acc[1][5]);
            acc[2][5] = ffma2(a2, w5, acc[2][5]);
            acc[3][5] = ffma2(a3, w5, acc[3][5]);
        }

        // store prefetched tile into other buffer
        if (kt + 1 < NKT_) {
            int nxt = cur ^ 1;
#pragma unroll
            for (int q = 0; q < 2; q++) {
                int tok = s_tok0 + q * 32;
                sa[nxt][s_kq + 0][tok] = pa[q].x;
                sa[nxt][s_kq + 1][tok] = pa[q].y;
                sa[nxt][s_kq + 2][tok] = pa[q].z;
                sa[nxt][s_kq + 3][tok] = pa[q].w;
            }
#pragma unroll
            for (int q = 0; q < 12; q++)
                *reinterpret_cast<ull*>(&sw[nxt][s_k][2 * (s_g + q * 8)]) = pack2(pw[q], pw[q]);
        }
        __syncthreads();
    }

    // epilogue: 8 tokens x 6 g -> g_xp (b,t,g)
#pragma unroll
    for (int p = 0; p < 4; p++) {
        int tok0 = base + tb + 2 * p;
        float lo[6], hi[6];
#pragma unroll
        for (int j = 0; j < 6; j++) {
            float2 v = unpack2(acc[p][j]);
            lo[j] = v.x + bias[j];
            hi[j] = v.y + bias[j];
        }
        int b0 = tok0 & (B_ - 1), t0 = tok0 >> 6;
        int b1v = (tok0 + 1) & (B_ - 1), t1v = (tok0 + 1) >> 6;
        float2* o0 = reinterpret_cast<float2*>(g_xp + ((size_t)b0 * H_ + t0) * G3_ + gbase);
        float2* o1 = reinterpret_cast<float2*>(g_xp + ((size_t)b1v * H_ + t1v) * G3_ + gbase);
        o0[0] = make_float2(lo[0], lo[1]);
        o0[1] = make_float2(lo[2], lo[3]);
        o0[2] = make_float2(lo[4], lo[5]);
        o1[0] = make_float2(hi[0], hi[1]);
        o1[1] = make_float2(hi[2], hi[3]);
        o1[2] = make_float2(hi[4], hi[5]);
    }
}

// =====================================================================
// Kernel 3: GRU scan. 1 warp per batch; critical-path-ordered gates,
// tanh.approx activations (single MUFU each).
// =====================================================================
__global__ void __launch_bounds__(32) k_gru(const float* __restrict__ w_hh,
                                            const float* __restrict__ b_hh)
{
    __shared__ __align__(16) float hb[2][GH_];
    int b = blockIdx.x;
    int l = threadIdx.x;

    ull wr2[16], wz2[16], wn2[16];
    const float2* wr = reinterpret_cast<const float2*>(w_hh + (0 * GH_ + l) * GH_);
    const float2* wz = reinterpret_cast<const float2*>(w_hh + (1 * GH_ + l) * GH_);
    const float2* wn = reinterpret_cast<const float2*>(w_hh + (2 * GH_ + l) * GH_);
#pragma unroll
    for (int k = 0; k < 16; k++) {
        float2 a = wr[k]; wr2[k] = pack2(a.x, a.y);
        float2 c = wz[k]; wz2[k] = pack2(c.x, c.y);
        float2 d = wn[k]; wn2[k] = pack2(d.x, d.y);
    }
    float br = b_hh[l], bz = b_hh[GH_ + l], bn = b_hh[2 * GH_ + l];

    float h = 0.0f;
    const float* xpb = g_xp + (size_t)b * H_ * G3_;
    float* encb = g_enc + (size_t)b * H_ * GH_;

    float xr0 = xpb[l],        xz0 = xpb[GH_ + l],        xn0 = xpb[2 * GH_ + l];
    float xr1 = xpb[G3_ + l],  xz1 = xpb[G3_ + GH_ + l],  xn1 = xpb[G3_ + 2 * GH_ + l];

    for (int t = 0; t < H_; t++) {
        float xr2 = 0.f, xz2 = 0.f, xn2 = 0.f;
        if (t + 2 < H_) {
            const float* row = xpb + (size_t)(t + 2) * G3_;
            xr2 = row[l]; xz2 = row[GH_ + l]; xn2 = row[2 * GH_ + l];
        }

        hb[t & 1][l] = h;
        __syncwarp();
        const ulonglong2* hp = reinterpret_cast<const ulonglong2*>(&hb[t & 1][0]);
        ulonglong2 hv[8];
#pragma unroll
        for (int kk = 0; kk < 8; kk++) hv[kk] = hp[kk];

        // --- r and n gate matvecs first (critical path to ng) ---
        ull ar0 = 0ull, ar1 = 0ull, an0 = 0ull, an1 = 0ull;
#pragma unroll
        for (int kk = 0; kk < 8; kk++) {
            ar0 = ffma2(hv[kk].x, wr2[2 * kk],     ar0);
            an0 = ffma2(hv[kk].x, wn2[2 * kk],     an0);
            ar1 = ffma2(hv[kk].y, wr2[2 * kk + 1], ar1);
            an1 = ffma2(hv[kk].y, wn2[2 * kk + 1], an1);
        }
        float2 rr = unpack2(fadd2(ar0, ar1));
        float2 nn = unpack2(fadd2(an0, an1));
        float ar = rr.x + rr.y + br;
        float an = nn.x + nn.y + bn;
        float rg = fsig(xr0 + ar);           // MUFU overlaps z-gate issue below

        // --- z gate matvec (overlaps rg's MUFU latency) ---
        ull az0 = 0ull, az1 = 0ull;
#pragma unroll
        for (int kk = 0; kk < 8; kk++) {
            az0 = ffma2(hv[kk].x, wz2[2 * kk],     az0);
            az1 = ffma2(hv[kk].y, wz2[2 * kk + 1], az1);
        }
        float2 zz = unpack2(fadd2(az0, az1));
        float az = zz.x + zz.y + bz;

        float ng = tanha(fmaf(rg, an, xn0));
        float zg = fsig(xz0 + az);           // overlaps ng's MUFU
        h = fmaf(zg, h - ng, ng);

        encb[t * GH_ + l] = h;
        xr0 = xr1; xz0 = xz1; xn0 = xn1;
        xr1 = xr2; xz1 = xz2; xn1 = xn2;
    }
}

// =====================================================================
// Kernel 4: attention scores — one thread per token, LDS.128 weight loads,
// split accumulators, tanh.approx
// =====================================================================
__global__ void __launch_bounds__(128) k_scores(
    const float* __restrict__ w1, const float* __restrict__ b1,
    const float* __restrict__ w2, const float* __restrict__ b2)
{
    __shared__ __align__(16) float sw1[GH_ * GH_];
    __shared__ __align__(16) float sw2[GH_ * GH_];
    __shared__ float sb1[GH_], sb2[GH_];

    int tid = threadIdx.x;
#pragma unroll
    for (int q = 0; q < 8; q++) {
        sw1[q * 128 + tid] = w1[q * 128 + tid];
        sw2[q * 128 + tid] = w2[q * 128 + tid];
    }
    if (tid < GH_) { sb1[tid] = b1[tid]; sb2[tid] = b2[tid]; }
    __syncthreads();

    int tok = blockIdx.x * 128 + tid;
    const float* erow = g_enc + (size_t)tok * GH_;

    ull e2[16];
#pragma unroll
    for (int i = 0; i < 8; i++) {
        ulonglong2 v = reinterpret_cast<const ulonglong2*>(erow)[i];
        e2[2 * i] = v.x; e2[2 * i + 1] = v.y;
    }

    // layer 1: hid_j = tanh(e . w1[j] + b1[j])
    ull h2[16];
#pragma unroll 4
    for (int j = 0; j < GH_; j += 2) {
        const ulonglong2* wA = reinterpret_cast<const ulonglong2*>(sw1 + j * GH_);
        const ulonglong2* wB = reinterpret_cast<const ulonglong2*>(sw1 + (j + 1) * GH_);
        ull a0 = 0ull, a1 = 0ull, c0 = 0ull, c1 = 0ull;
#pragma unroll
        for (int k = 0; k < 8; k++) {
            ulonglong2 wa = wA[k], wb = wB[k];
            a0 = ffma2(e2[2 * k],     wa.x, a0);
            a1 = ffma2(e2[2 * k + 1], wa.y, a1);
            c0 = ffma2(e2[2 * k],     wb.x, c0);
            c1 = ffma2(e2[2 * k + 1], wb.y, c1);
        }
        float2 fa = unpack2(fadd2(a0, a1));
        float2 fc = unpack2(fadd2(c0, c1));
        float ha  = tanha(fa.x + fa.y + sb1[j]);
        float hbv = tanha(fc.x + fc.y + sb1[j + 1]);
        h2[j >> 1] = pack2(ha, hbv);
    }

    // layer 2: att_g = hid . w2[g] + b2[g]
    float outv[GH_];
#pragma unroll 4
    for (int g = 0; g < GH_; g += 2) {
        const ulonglong2* wA = reinterpret_cast<const ulonglong2*>(sw2 + g * GH_);
        const ulonglong2* wB = reinterpret_cast<const ulonglong2*>(sw2 + (g + 1) * GH_);
        ull a0 = 0ull, a1 = 0ull, c0 = 0ull, c1 = 0ull;
#pragma unroll
        for (int k = 0; k < 8; k++) {
            ulonglong2 wa = wA[k], wb = wB[k];
            a0 = ffma2(h2[2 * k],     wa.x, a0);
            a1 = ffma2(h2[2 * k + 1], wa.y, a1);
            c0 = ffma2(h2[2 * k],     wb.x, c0);
            c1 = ffma2(h2[2 * k + 1], wb.y, c1);
        }
        float2 fa = unpack2(fadd2(a0, a1));
        float2 fc = unpack2(fadd2(c0, c1));
        outv[g]     = fa.x + fa.y + sb2[g];
        outv[g + 1] = fc.x + fc.y + sb2[g + 1];
    }

    float* arow = g_att + (size_t)tok * GH_;
#pragma unroll
    for (int i = 0; i < 8; i++)
        reinterpret_cast<float4*>(arow)[i] =
            make_float4(outv[4 * i], outv[4 * i + 1], outv[4 * i + 2], outv[4 * i + 3]);
}

// =====================================================================
// Kernel 5: softmax over t + pool + head. block per batch, 512 threads.
// 64 t-partitions x 8 g-threads (float4 per thread).
// =====================================================================
__device__ __forceinline__ float4 max4(float4 a, float4 b) {
    return make_float4(fmaxf(a.x, b.x), fmaxf(a.y, b.y), fmaxf(a.z, b.z), fmaxf(a.w, b.w));
}
__global__ void __launch_bounds__(512) k_pool(
    const float* __restrict__ w3, const float* __restrict__ b3,
    float* __restrict__ out)
{
    int b    = blockIdx.x;
    int tid  = threadIdx.x;
    int part = tid >> 3;         // 0..63
    int gq   = tid & 7;          // float4 index into 32 channels
    int wid  = tid >> 5;

    const float4* encb = reinterpret_cast<const float4*>(g_enc + (size_t)b * H_ * GH_);
    const float4* attb = reinterpret_cast<const float4*>(g_att + (size_t)b * H_ * GH_);

    __shared__ float4 red[16][8];     // per-warp partials
    __shared__ float4 mg4s[8];
    __shared__ float pooled[GH_];

    // ---- pass 1: max over t ----
    float4 m = make_float4(-1e30f, -1e30f, -1e30f, -1e30f);
    for (int t = part; t < H_; t += 64)
        m = max4(m, attb[t * 8 + gq]);
    // warp has 4 parts x 8 gq; reduce parts via shfl_xor 8,16
#pragma unroll
    for (int s = 8; s <= 16; s <<= 1) {
        m.x = fmaxf(m.x, __shfl_xor_sync(0xffffffffu, m.x, s));
        m.y = fmaxf(m.y, __shfl_xor_sync(0xffffffffu, m.y, s));
        m.z = fmaxf(m.z, __shfl_xor_sync(0xffffffffu, m.z, s));
        m.w = fmaxf(m.w, __shfl_xor_sync(0xffffffffu, m.w, s));
    }
    if ((tid & 31) < 8) red[wid][gq] = m;
    __syncthreads();
    if (tid < 8) {
        float4 mm = red[0][tid];
#pragma unroll
        for (int p = 1; p < 16; p++) mm = max4(mm, red[p][tid]);
        mg4s[tid] = mm;
    }
    __syncthreads();
    float4 mg = mg4s[gq];

    // ---- pass 2: exp-sum + weighted pool ----
    float4 se = make_float4(0.f, 0.f, 0.f, 0.f);
    float4 pw = make_float4(0.f, 0.f, 0.f, 0.f);
    for (int t = part; t < H_; t += 64) {
        float4 a = attb[t * 8 + gq];
        float4 e = encb[t * 8 + gq];
        float ex0 = __expf(a.x - mg.x);
        float ex1 = __expf(a.y - mg.y);
        float ex2v = __expf(a.z - mg.z);
        float ex3 = __expf(a.w - mg.w);
        se.x += ex0; se.y += ex1; se.z += ex2v; se.w += ex3;
        pw.x = fmaf(ex0, e.x, pw.x);
        pw.y = fmaf(ex1, e.y, pw.y);
        pw.z = fmaf(ex2v, e.z, pw.z);
        pw.w = fmaf(ex3, e.w, pw.w);
    }
#pragma unroll
    for (int s = 8; s <= 16; s <<= 1) {
        se.x += __shfl_xor_sync(0xffffffffu, se.x, s);
        se.y += __shfl_xor_sync(0xffffffffu, se.y, s);
        se.z += __shfl_xor_sync(0xffffffffu, se.z, s);
        se.w += __shfl_xor_sync(0xffffffffu, se.w, s);
        pw.x += __shfl_xor_sync(0xffffffffu, pw.x, s);
        pw.y += __shfl_xor_sync(0xffffffffu, pw.y, s);
        pw.z += __shfl_xor_sync(0xffffffffu, pw.z, s);
        pw.w += __shfl_xor_sync(0xffffffffu, pw.w, s);
    }
    __syncthreads();   // red[] reuse
    if ((tid & 31) < 8) red[wid][gq] = se;
    __syncthreads();
    __shared__ float4 redp[16][8];
    if ((tid & 31) < 8) redp[wid][gq] = pw;
    __syncthreads();
    if (tid < 8) {
        float4 ts = red[0][tid];
        float4 tp = redp[0][tid];
#pragma unroll
        for (int p = 1; p < 16; p++) {
            float4 s1 = red[p][tid];
            float4 p1 = redp[p][tid];
            ts.x += s1.x; ts.y += s1.y; ts.z += s1.z; ts.w += s1.w;
            tp.x += p1.x; tp.y += p1.y; tp.z += p1.z; tp.w += p1.w;
        }
        pooled[tid * 4 + 0] = tp.x / ts.x;
        pooled[tid * 4 + 1] = tp.y / ts.y;
        pooled[tid * 4 + 2] = tp.z / ts.z;
        pooled[tid * 4 + 3] = tp.w / ts.w;
    }
    __syncthreads();

    if (tid < 64) {
        int o  = tid >> 5;
        int gg = tid & 31;
        float v = pooled[gg] * __ldg(&w3[o * GH_ + gg]);
#pragma unroll
        for (int s = 16; s > 0; s >>= 1)
            v += __shfl_xor_sync(0xffffffffu, v, s);
        if (gg == 0)
            out[b * 2 + o] = v + __ldg(&b3[o]);
    }
}

// =====================================================================
extern "C" void kernel_launch(void* const* d_in, const int* in_sizes, int n_in,
                              void* d_out, int out_size)
{
    const float* x     = (const float*)d_in[0];
    const float* p_w   = (const float*)d_in[1];
    const float* p_b   = (const float*)d_in[2];
    const float* dcn_w = (const float*)d_in[3];
    const float* dcn_b = (const float*)d_in[4];
    const float* w_ih  = (const float*)d_in[5];
    const float* w_hh  = (const float*)d_in[6];
    const float* b_ih  = (const float*)d_in[7];
    const float* b_hh  = (const float*)d_in[8];
    const float* w1    = (const float*)d_in[9];
    const float* b1    = (const float*)d_in[10];
    const float* w2    = (const float*)d_in[11];
    const float* b2    = (const float*)d_in[12];
    const float* w3    = (const float*)d_in[13];
    const float* b3    = (const float*)d_in[14];
    float* out = (float*)d_out;

    {
        int total   = B_ * H_ * WO_;
        int threads = 128;
        int blocks  = (total + threads - 1) / threads;
        k_deform<<<blocks, threads>>>(x, p_w, p_b, dcn_w, dcn_b);
    }
    {
        k_gemm<<<NTOK_ / TM_, 128>>>(w_ih, b_ih);   // 510 blocks
    }
    {
        k_gru<<<B_, GH_>>>(w_hh, b_hh);
    }
    {
        k_scores<<<NTOK_ / 128, 128>>>(w1, b1, w2, b2);  // 255 blocks
    }
    {
        k_pool<<<B_, 512>>>(w3, b3, out);
    }
}

// round 5
// speedup vs baseline: 2.6563x; 1.0093x over previous
#include <cuda_runtime.h>
#include <cuda_bf16.h>
#include <math.h>

// ---------------- problem constants ----------------
#define B_      64
#define T_      512
#define WIN_    40
#define KS_     3
#define NPT_    9          // KS*KS
#define CF_     8
#define H_      510        // T - 2
#define WO_     38         // WIN - 2
#define GIN_    304        // WO_*CF_
#define GH_     32
#define G3_     96         // 3*GH
#define NTOK_   (H_ * B_)  // 32640
#define HTOK_   (NTOK_ / 2) // 16320

typedef unsigned long long ull;

// ---------------- scratch (device globals; no cudaMalloc allowed) -------------
__device__ float g_seq[NTOK_ * GIN_];     // (t,b,f)
__device__ float g_xp [NTOK_ * G3_];      // (b,t,g)
__device__ float g_enc[B_ * H_ * GH_];    // (b,t,g)
__device__ float g_att[B_ * H_ * GH_];    // (b,t,g)
__device__ float g_wt [GIN_ * 2 * G3_];   // [k][2g|2g+1] duplicated, k-major

// ---------------- f32x2 packed math helpers ----------------
__device__ __forceinline__ ull ffma2(ull a, ull b, ull c) {
    ull d;
    asm("fma.rn.f32x2 %0, %1, %2, %3;" : "=l"(d) : "l"(a), "l"(b), "l"(c));
    return d;
}
__device__ __forceinline__ ull fadd2(ull a, ull b) {
    ull d;
    asm("add.rn.f32x2 %0, %1, %2;" : "=l"(d) : "l"(a), "l"(b));
    return d;
}
__device__ __forceinline__ ull pack2(float x, float y) {
    ull v;
    asm("mov.b64 %0, {%1, %2};" : "=l"(v) : "f"(x), "f"(y));
    return v;
}
__device__ __forceinline__ float2 unpack2(ull v) {
    float2 r;
    asm("mov.b64 {%0, %1}, %2;" : "=f"(r.x), "=f"(r.y) : "l"(v));
    return r;
}

// ---------------- fast activations via tanh.approx ----------------
__device__ __forceinline__ float tanha(float x) {
    float r; asm("tanh.approx.f32 %0, %1;" : "=f"(r) : "f"(x)); return r;
}
__device__ __forceinline__ float fsig(float x) {
    return fmaf(0.5f, tanha(0.5f * x), 0.5f);
}

// =====================================================================
// Kernel 0: W transpose + duplicate: g_wt[k][2g] = g_wt[k][2g+1] = w_ih[g][k]
// =====================================================================
__global__ void k_wprep(const float* __restrict__ w_ih)
{
    int idx = blockIdx.x * blockDim.x + threadIdx.x;   // over g*GIN + k
    if (idx >= G3_ * GIN_) return;
    int g = idx / GIN_;
    int k = idx - g * GIN_;
    float v = w_ih[idx];
    *reinterpret_cast<float2*>(&g_wt[k * (2 * G3_) + 2 * g]) = make_float2(v, v);
}

// =====================================================================
// Kernel 1: deformable conv -> g_seq (t,b, w*8+c)
// =====================================================================
__global__ void k_deform(const float* __restrict__ x,
                         const float* __restrict__ p_w,
                         const float* __restrict__ p_b,
                         const float* __restrict__ dcn_w,
                         const float* __restrict__ dcn_b)
{
    __shared__ float s_pw[2 * NPT_ * NPT_];
    __shared__ float s_pb[2 * NPT_];
    __shared__ float s_dw[CF_ * NPT_];
    __shared__ float s_db[CF_];

    int tid = threadIdx.x;
    for (int i = tid; i < 2 * NPT_ * NPT_; i += blockDim.x) s_pw[i] = p_w[i];
    for (int i = tid; i < 2 * NPT_;       i += blockDim.x) s_pb[i] = p_b[i];
    for (int i = tid; i < CF_ * NPT_;     i += blockDim.x) s_dw[i] = dcn_w[i];
    for (int i = tid; i < CF_;            i += blockDim.x) s_db[i] = dcn_b[i];
    __syncthreads();

    int idx = blockIdx.x * blockDim.x + tid;
    const int total = B_ * H_ * WO_;
    if (idx >= total) return;

    int w  = idx % WO_;
    int b  = (idx / WO_) % B_;
    int t  = idx / (WO_ * B_);

    const float* xb = x + b * (T_ * WIN_);

    float patch[NPT_];
#pragma unroll
    for (int ky = 0; ky < KS_; ky++)
#pragma unroll
        for (int kx = 0; kx < KS_; kx++)
            patch[ky * KS_ + kx] = xb[(t + ky) * WIN_ + (w + kx)];

    float off[2 * NPT_];
#pragma unroll
    for (int o = 0; o < 2 * NPT_; o++) off[o] = s_pb[o];
#pragma unroll
    for (int k = 0; k < NPT_; k++) {
        float pv = patch[k];
#pragma unroll
        for (int o = 0; o < 2 * NPT_; o++)
            off[o] = fmaf(pv, s_pw[o * NPT_ + k], off[o]);
    }

    float acc[CF_];
#pragma unroll
    for (int c = 0; c < CF_; c++) acc[c] = s_db[c];

#pragma unroll
    for (int n = 0; n < NPT_; n++) {
        float py = off[n]        + (float)(n / 3 - 1) + (float)(t + 1);
        float px = off[NPT_ + n] + (float)(n % 3 - 1) + (float)(w + 1);
        py = fminf(fmaxf(py, 0.0f), (float)(T_ - 1));
        px = fminf(fmaxf(px, 0.0f), (float)(WIN_ - 1));
        int y0 = (int)floorf(py);
        int x0 = (int)floorf(px);
        int y1 = min(y0 + 1, T_ - 1);
        int x1 = min(x0 + 1, WIN_ - 1);
        float wy = py - (float)y0;
        float wx = px - (float)x0;
        float g00 = __ldg(&xb[y0 * WIN_ + x0]);
        float g01 = __ldg(&xb[y0 * WIN_ + x1]);
        float g10 = __ldg(&xb[y1 * WIN_ + x0]);
        float g11 = __ldg(&xb[y1 * WIN_ + x1]);
        float top = g00 + wx * (g01 - g00);
        float bot = g10 + wx * (g11 - g10);
        float s   = top + wy * (bot - top);
#pragma unroll
        for (int c = 0; c < CF_; c++)
            acc[c] = fmaf(s, s_dw[c * NPT_ + n], acc[c]);
    }

    float* dst = g_seq + (size_t)(t * B_ + b) * GIN_ + w * CF_;
    *reinterpret_cast<float4*>(dst)     = make_float4(acc[0], acc[1], acc[2], acc[3]);
    *reinterpret_cast<float4*>(dst + 4) = make_float4(acc[4], acc[5], acc[6], acc[7]);
}

// =====================================================================
// Kernel 2: GEMM 32640x96x304, fma.rn.f32x2, double-buffered smem,
// coalesced W staging from pre-transposed g_wt.
// =====================================================================
#define TM_ 64
#define KT_ 16
#define NKT_ (GIN_ / KT_)     // 19
#define SA_W (TM_ + 2)        // 66 (conflict-free transpose stores)
#define SW_W (2 * G3_ + 4)    // 196 (16B-aligned rows, float4 staging)
__global__ void __launch_bounds__(128) k_gemm(const float* __restrict__ b_ih)
{
    __shared__ __align__(16) float sa[2][KT_][SA_W];
    __shared__ __align__(16) float sw[2][KT_][SW_W];

    int tid = threadIdx.x;
    int tg  = tid >> 4;
    int gg  = tid & 15;
    int tb  = tg * 8;
    int gbase = gg * 6;
    int base = blockIdx.x * TM_;

    // A staging indices
    int s_tok0 = tid >> 2;
    int s_kq   = (tid & 3) * 4;
    // W staging indices: 768 float4 per tile = 6 per thread; 48 float4 per k-row
    int w_k0   = tid / 48;          // advance by (128/48) rows per q... use flat idx

    float bias[6];
#pragma unroll
    for (int j = 0; j < 6; j++) bias[j] = __ldg(&b_ih[gbase + j]);

    ull acc[4][6];
#pragma unroll
    for (int p = 0; p < 4; p++)
#pragma unroll
        for (int j = 0; j < 6; j++) acc[p][j] = 0ull;

    float4 pa[2];
    float4 pw[6];
    (void)w_k0;

    // prologue: load tile 0
    {
#pragma unroll
        for (int q = 0; q < 2; q++)
            pa[q] = *reinterpret_cast<const float4*>(
                g_seq + (size_t)(base + s_tok0 + q * 32) * GIN_ + s_kq);
        const float4* wsrc = reinterpret_cast<const float4*>(g_wt);  // [k][192]
#pragma unroll
        for (int q = 0; q < 6; q++) {
            int i = q * 128 + tid;              // 0..767
            pw[q] = wsrc[i];                    // rows of 48 float4
        }
    }
    {
#pragma unroll
        for (int q = 0; q < 2; q++) {
            int tok = s_tok0 + q * 32;
            sa[0][s_kq + 0][tok] = pa[q].x;
            sa[0][s_kq + 1][tok] = pa[q].y;
            sa[0][s_kq + 2][tok] = pa[q].z;
            sa[0][s_kq + 3][tok] = pa[q].w;
        }
#pragma unroll
        for (int q = 0; q < 6; q++) {
            int i = q * 128 + tid;
            int k = i / 48;
            int c4 = i - k * 48;
            *reinterpret_cast<float4*>(&sw[0][k][c4 * 4]) = pw[q];
        }
    }
    __syncthreads();

    for (int kt = 0; kt < NKT_; kt++) {
        int cur = kt & 1;
        if (kt + 1 < NKT_) {
            int k0 = (kt + 1) * KT_;
#pragma unroll
            for (int q = 0; q < 2; q++)
                pa[q] = *reinterpret_cast<const float4*>(
                    g_seq + (size_t)(base + s_tok0 + q * 32) * GIN_ + k0 + s_kq);
            const float4* wsrc = reinterpret_cast<const float4*>(g_wt + k0 * (2 * G3_));
#pragma unroll
            for (int q = 0; q < 6; q++)
                pw[q] = wsrc[q * 128 + tid];
        }

#pragma unroll
        for (int k = 0; k < KT_; k++) {
            const ull* ap = reinterpret_cast<const ull*>(&sa[cur][k][tb]);
            ull a0 = ap[0], a1 = ap[1], a2 = ap[2], a3 = ap[3];
            const ull* wp = reinterpret_cast<const ull*>(&sw[cur][k][2 * gbase]);
            ull w0 = wp[0], w1 = wp[1], w2 = wp[2], w3 = wp[3], w4 = wp[4], w5 = wp[5];
            acc[0][0] = ffma2(a0, w0, acc[0][0]);
            acc[1][0] = ffma2(a1, w0, acc[1][0]);
            acc[2][0] = ffma2(a2, w0, acc[2][0]);
            acc[3][0] = ffma2(a3, w0, acc[3][0]);
            acc[0][1] = ffma2(a0, w1, acc[0][1]);
            acc[1][1] = ffma2(a1, w1, acc[1][1]);
            acc[2][1] = ffma2(a2, w1, acc[2][1]);
            acc[3][1] = ffma2(a3, w1, acc[3][1]);
            acc[0][2] = ffma2(a0, w2, acc[0][2]);
            acc[1][2] = ffma2(a1, w2, acc[1][2]);
            acc[2][2] = ffma2(a2, w2, acc[2][2]);
            acc[3][2] = ffma2(a3, w2, acc[3][2]);
            acc[0][3] = ffma2(a0, w3, acc[0][3]);
            acc[1][3] = ffma2(a1, w3, acc[1][3]);
            acc[2][3] = ffma2(a2, w3, acc[2][3]);
            acc[3][3] = ffma2(a3, w3, acc[3][3]);
            acc[0][4] = ffma2(a0, w4, acc[0][4]);
            acc[1][4] = ffma2(a1, w4, acc[1][4]);
            acc[2][4] = ffma2(a2, w4, acc[2][4]);
            acc[3][4] = ffma2(a3, w4, acc[3][4]);
            acc[0][5] = ffma2(a0, w5, acc[0][5]);
            acc[1][5] = ffma2(a1, w5, acc[1][5]);
            acc[2][5] = ffma2(a2, w5, acc[2][5]);
            acc[3][5] = ffma2(a3, w5, acc[3][5]);
        }

        if (kt + 1 < NKT_) {
            int nxt = cur ^ 1;
#pragma unroll
            for (int q = 0; q < 2; q++) {
                int tok = s_tok0 + q * 32;
                sa[nxt][s_kq + 0][tok] = pa[q].x;
                sa[nxt][s_kq + 1][tok] = pa[q].y;
                sa[nxt][s_kq + 2][tok] = pa[q].z;
                sa[nxt][s_kq + 3][tok] = pa[q].w;
            }
#pragma unroll
            for (int q = 0; q < 6; q++) {
                int i = q * 128 + tid;
                int k = i / 48;
                int c4 = i - k * 48;
                *reinterpret_cast<float4*>(&sw[nxt][k][c4 * 4]) = pw[q];
            }
        }
        __syncthreads();
    }

    // epilogue: 8 tokens x 6 g -> g_xp (b,t,g)
#pragma unroll
    for (int p = 0; p < 4; p++) {
        int tok0 = base + tb + 2 * p;
        float lo[6], hi[6];
#pragma unroll
        for (int j = 0; j < 6; j++) {
            float2 v = unpack2(acc[p][j]);
            lo[j] = v.x + bias[j];
            hi[j] = v.y + bias[j];
        }
        int b0 = tok0 & (B_ - 1), t0 = tok0 >> 6;
        int b1v = (tok0 + 1) & (B_ - 1), t1v = (tok0 + 1) >> 6;
        float2* o0 = reinterpret_cast<float2*>(g_xp + ((size_t)b0 * H_ + t0) * G3_ + gbase);
        float2* o1 = reinterpret_cast<float2*>(g_xp + ((size_t)b1v * H_ + t1v) * G3_ + gbase);
        o0[0] = make_float2(lo[0], lo[1]);
        o0[1] = make_float2(lo[2], lo[3]);
        o0[2] = make_float2(lo[4], lo[5]);
        o1[0] = make_float2(hi[0], hi[1]);
        o1[1] = make_float2(hi[2], hi[3]);
        o1[2] = make_float2(hi[4], hi[5]);
    }
}

// =====================================================================
// Kernel 3: GRU scan. 1 warp per batch; critical-path-ordered gates.
// =====================================================================
__global__ void __launch_bounds__(32) k_gru(const float* __restrict__ w_hh,
                                            const float* __restrict__ b_hh)
{
    __shared__ __align__(16) float hb[2][GH_];
    int b = blockIdx.x;
    int l = threadIdx.x;

    ull wr2[16], wz2[16], wn2[16];
    const float2* wr = reinterpret_cast<const float2*>(w_hh + (0 * GH_ + l) * GH_);
    const float2* wz = reinterpret_cast<const float2*>(w_hh + (1 * GH_ + l) * GH_);
    const float2* wn = reinterpret_cast<const float2*>(w_hh + (2 * GH_ + l) * GH_);
#pragma unroll
    for (int k = 0; k < 16; k++) {
        float2 a = wr[k]; wr2[k] = pack2(a.x, a.y);
        float2 c = wz[k]; wz2[k] = pack2(c.x, c.y);
        float2 d = wn[k]; wn2[k] = pack2(d.x, d.y);
    }
    float br = b_hh[l], bz = b_hh[GH_ + l], bn = b_hh[2 * GH_ + l];

    float h = 0.0f;
    const float* xpb = g_xp + (size_t)b * H_ * G3_;
    float* encb = g_enc + (size_t)b * H_ * GH_;

    float xr0 = xpb[l],        xz0 = xpb[GH_ + l],        xn0 = xpb[2 * GH_ + l];
    float xr1 = xpb[G3_ + l],  xz1 = xpb[G3_ + GH_ + l],  xn1 = xpb[G3_ + 2 * GH_ + l];

    for (int t = 0; t < H_; t++) {
        float xr2 = 0.f, xz2 = 0.f, xn2 = 0.f;
        if (t + 2 < H_) {
            const float* row = xpb + (size_t)(t + 2) * G3_;
            xr2 = row[l]; xz2 = row[GH_ + l]; xn2 = row[2 * GH_ + l];
        }

        hb[t & 1][l] = h;
        __syncwarp();
        const ulonglong2* hp = reinterpret_cast<const ulonglong2*>(&hb[t & 1][0]);
        ulonglong2 hv[8];
#pragma unroll
        for (int kk = 0; kk < 8; kk++) hv[kk] = hp[kk];

        ull ar0 = 0ull, ar1 = 0ull, an0 = 0ull, an1 = 0ull;
#pragma unroll
        for (int kk = 0; kk < 8; kk++) {
            ar0 = ffma2(hv[kk].x, wr2[2 * kk],     ar0);
            an0 = ffma2(hv[kk].x, wn2[2 * kk],     an0);
            ar1 = ffma2(hv[kk].y, wr2[2 * kk + 1], ar1);
            an1 = ffma2(hv[kk].y, wn2[2 * kk + 1], an1);
        }
        float2 rr = unpack2(fadd2(ar0, ar1));
        float2 nn = unpack2(fadd2(an0, an1));
        float ar = rr.x + rr.y + br;
        float an = nn.x + nn.y + bn;
        float rg = fsig(xr0 + ar);

        ull az0 = 0ull, az1 = 0ull;
#pragma unroll
        for (int kk = 0; kk < 8; kk++) {
            az0 = ffma2(hv[kk].x, wz2[2 * kk],     az0);
            az1 = ffma2(hv[kk].y, wz2[2 * kk + 1], az1);
        }
        float2 zz = unpack2(fadd2(az0, az1));
        float az = zz.x + zz.y + bz;

        float ng = tanha(fmaf(rg, an, xn0));
        float zg = fsig(xz0 + az);
        h = fmaf(zg, h - ng, ng);

        encb[t * GH_ + l] = h;
        xr0 = xr1; xz0 = xz1; xn0 = xn1;
        xr1 = xr2; xz1 = xz2; xn1 = xn2;
    }
}

// =====================================================================
// Kernel 4: attention scores — 2 tokens per thread (tok, tok+HTOK),
// uniform weight LDS shared across both, tanh.approx
// =====================================================================
__global__ void __launch_bounds__(128) k_scores(
    const float* __restrict__ w1, const float* __restrict__ b1,
    const float* __restrict__ w2, const float* __restrict__ b2)
{
    __shared__ __align__(16) float sw1[GH_ * GH_];
    __shared__ __align__(16) float sw2[GH_ * GH_];
    __shared__ float sb1[GH_], sb2[GH_];

    int tid = threadIdx.x;
#pragma unroll
    for (int q = 0; q < 8; q++) {
        sw1[q * 128 + tid] = w1[q * 128 + tid];
        sw2[q * 128 + tid] = w2[q * 128 + tid];
    }
    if (tid < GH_) { sb1[tid] = b1[tid]; sb2[tid] = b2[tid]; }
    __syncthreads();

    int tok = blockIdx.x * 128 + tid;
    if (tok >= HTOK_) return;
    const float* erowA = g_enc + (size_t)tok * GH_;
    const float* erowB = g_enc + (size_t)(tok + HTOK_) * GH_;

    ull eA[16], eB[16];
#pragma unroll
    for (int i = 0; i < 8; i++) {
        ulonglong2 va = reinterpret_cast<const ulonglong2*>(erowA)[i];
        ulonglong2 vb = reinterpret_cast<const ulonglong2*>(erowB)[i];
        eA[2 * i] = va.x; eA[2 * i + 1] = va.y;
        eB[2 * i] = vb.x; eB[2 * i + 1] = vb.y;
    }

    // layer 1
    ull hA[16], hB[16];
#pragma unroll 2
    for (int j = 0; j < GH_; j += 2) {
        const ulonglong2* wA = reinterpret_cast<const ulonglong2*>(sw1 + j * GH_);
        const ulonglong2* wB = reinterpret_cast<const ulonglong2*>(sw1 + (j + 1) * GH_);
        ull a0 = 0ull, a1 = 0ull, c0 = 0ull, c1 = 0ull;
        ull d0 = 0ull, d1 = 0ull, f0 = 0ull, f1 = 0ull;
#pragma unroll
        for (int k = 0; k < 8; k++) {
            ulonglong2 wa = wA[k], wb = wB[k];
            a0 = ffma2(eA[2 * k],     wa.x, a0);
            a1 = ffma2(eA[2 * k + 1], wa.y, a1);
            c0 = ffma2(eA[2 * k],     wb.x, c0);
            c1 = ffma2(eA[2 * k + 1], wb.y, c1);
            d0 = ffma2(eB[2 * k],     wa.x, d0);
            d1 = ffma2(eB[2 * k + 1], wa.y, d1);
            f0 = ffma2(eB[2 * k],     wb.x, f0);
            f1 = ffma2(eB[2 * k + 1], wb.y, f1);
        }
        float2 fa = unpack2(fadd2(a0, a1));
        float2 fc = unpack2(fadd2(c0, c1));
        float2 fd = unpack2(fadd2(d0, d1));
        float2 ff = unpack2(fadd2(f0, f1));
        hA[j >> 1] = pack2(tanha(fa.x + fa.y + sb1[j]), tanha(fc.x + fc.y + sb1[j + 1]));
        hB[j >> 1] = pack2(tanha(fd.x + fd.y + sb1[j]), tanha(ff.x + ff.y + sb1[j + 1]));
    }

    // layer 2
    float outA[GH_], outB[GH_];
#pragma unroll 2
    for (int g = 0; g < GH_; g += 2) {
        const ulonglong2* wA = reinterpret_cast<const ulonglong2*>(sw2 + g * GH_);
        const ulonglong2* wB = reinterpret_cast<const ulonglong2*>(sw2 + (g + 1) * GH_);
        ull a0 = 0ull, a1 = 0ull, c0 = 0ull, c1 = 0ull;
        ull d0 = 0ull, d1 = 0ull, f0 = 0ull, f1 = 0ull;
#pragma unroll
        for (int k = 0; k < 8; k++) {
            ulonglong2 wa = wA[k], wb = wB[k];
            a0 = ffma2(hA[2 * k],     wa.x, a0);
            a1 = ffma2(hA[2 * k + 1], wa.y, a1);
            c0 = ffma2(hA[2 * k],     wb.x, c0);
            c1 = ffma2(hA[2 * k + 1], wb.y, c1);
            d0 = ffma2(hB[2 * k],     wa.x, d0);
            d1 = ffma2(hB[2 * k + 1], wa.y, d1);
            f0 = ffma2(hB[2 * k],     wb.x, f0);
            f1 = ffma2(hB[2 * k + 1], wb.y, f1);
        }
        float2 fa = unpack2(fadd2(a0, a1));
        float2 fc = unpack2(fadd2(c0, c1));
        float2 fd = unpack2(fadd2(d0, d1));
        float2 ff = unpack2(fadd2(f0, f1));
        outA[g]     = fa.x + fa.y + sb2[g];
        outA[g + 1] = fc.x + fc.y + sb2[g + 1];
        outB[g]     = fd.x + fd.y + sb2[g];
        outB[g + 1] = ff.x + ff.y + sb2[g + 1];
    }

    float* arowA = g_att + (size_t)tok * GH_;
    float* arowB = g_att + (size_t)(tok + HTOK_) * GH_;
#pragma unroll
    for (int i = 0; i < 8; i++) {
        reinterpret_cast<float4*>(arowA)[i] =
            make_float4(outA[4 * i], outA[4 * i + 1], outA[4 * i + 2], outA[4 * i + 3]);
        reinterpret_cast<float4*>(arowB)[i] =
            make_float4(outB[4 * i], outB[4 * i + 1], outB[4 * i + 2], outB[4 * i + 3]);
    }
}

// =====================================================================
// Kernel 5: softmax over t + pool + head. block per batch, 512 threads.
// =====================================================================
__device__ __forceinline__ float4 max4(float4 a, float4 b) {
    return make_float4(fmaxf(a.x, b.x), fmaxf(a.y, b.y), fmaxf(a.z, b.z), fmaxf(a.w, b.w));
}
__global__ void __launch_bounds__(512) k_pool(
    const float* __restrict__ w3, const float* __restrict__ b3,
    float* __restrict__ out)
{
    int b    = blockIdx.x;
    int tid  = threadIdx.x;
    int part = tid >> 3;
    int gq   = tid & 7;
    int wid  = tid >> 5;

    const float4* encb = reinterpret_cast<const float4*>(g_enc + (size_t)b * H_ * GH_);
    const float4* attb = reinterpret_cast<const float4*>(g_att + (size_t)b * H_ * GH_);

    __shared__ float4 red[16][8];
    __shared__ float4 mg4s[8];
    __shared__ float pooled[GH_];

    float4 m = make_float4(-1e30f, -1e30f, -1e30f, -1e30f);
    for (int t = part; t < H_; t += 64)
        m = max4(m, attb[t * 8 + gq]);
#pragma unroll
    for (int s = 8; s <= 16; s <<= 1) {
        m.x = fmaxf(m.x, __shfl_xor_sync(0xffffffffu, m.x, s));
        m.y = fmaxf(m.y, __shfl_xor_sync(0xffffffffu, m.y, s));
        m.z = fmaxf(m.z, __shfl_xor_sync(0xffffffffu, m.z, s));
        m.w = fmaxf(m.w, __shfl_xor_sync(0xffffffffu, m.w, s));
    }
    if ((tid & 31) < 8) red[wid][gq] = m;
    __syncthreads();
    if (tid < 8) {
        float4 mm = red[0][tid];
#pragma unroll
        for (int p = 1; p < 16; p++) mm = max4(mm, red[p][tid]);
        mg4s[tid] = mm;
    }
    __syncthreads();
    float4 mg = mg4s[gq];

    float4 se = make_float4(0.f, 0.f, 0.f, 0.f);
    float4 pw = make_float4(0.f, 0.f, 0.f, 0.f);
    for (int t = part; t < H_; t += 64) {
        float4 a = attb[t * 8 + gq];
        float4 e = encb[t * 8 + gq];
        float ex0 = __expf(a.x - mg.x);
        float ex1 = __expf(a.y - mg.y);
        float ex2v = __expf(a.z - mg.z);
        float ex3 = __expf(a.w - mg.w);
        se.x += ex0; se.y += ex1; se.z += ex2v; se.w += ex3;
        pw.x = fmaf(ex0, e.x, pw.x);
        pw.y = fmaf(ex1, e.y, pw.y);
        pw.z = fmaf(ex2v, e.z, pw.z);
        pw.w = fmaf(ex3, e.w, pw.w);
    }
#pragma unroll
    for (int s = 8; s <= 16; s <<= 1) {
        se.x += __shfl_xor_sync(0xffffffffu, se.x, s);
        se.y += __shfl_xor_sync(0xffffffffu, se.y, s);
        se.z += __shfl_xor_sync(0xffffffffu, se.z, s);
        se.w += __shfl_xor_sync(0xffffffffu, se.w, s);
        pw.x += __shfl_xor_sync(0xffffffffu, pw.x, s);
        pw.y += __shfl_xor_sync(0xffffffffu, pw.y, s);
        pw.z += __shfl_xor_sync(0xffffffffu, pw.z, s);
        pw.w += __shfl_xor_sync(0xffffffffu, pw.w, s);
    }
    __syncthreads();
    if ((tid & 31) < 8) red[wid][gq] = se;
    __syncthreads();
    __shared__ float4 redp[16][8];
    if ((tid & 31) < 8) redp[wid][gq] = pw;
    __syncthreads();
    if (tid < 8) {
        float4 ts = red[0][tid];
        float4 tp = redp[0][tid];
#pragma unroll
        for (int p = 1; p < 16; p++) {
            float4 s1 = red[p][tid];
            float4 p1 = redp[p][tid];
            ts.x += s1.x; ts.y += s1.y; ts.z += s1.z; ts.w += s1.w;
            tp.x += p1.x; tp.y += p1.y; tp.z += p1.z; tp.w += p1.w;
        }
        pooled[tid * 4 + 0] = tp.x / ts.x;
        pooled[tid * 4 + 1] = tp.y / ts.y;
        pooled[tid * 4 + 2] = tp.z / ts.z;
        pooled[tid * 4 + 3] = tp.w / ts.w;
    }
    __syncthreads();

    if (tid < 64) {
        int o  = tid >> 5;
        int gg = tid & 31;
        float v = pooled[gg] * __ldg(&w3[o * GH_ + gg]);
#pragma unroll
        for (int s = 16; s > 0; s >>= 1)
            v += __shfl_xor_sync(0xffffffffu, v, s);
        if (gg == 0)
            out[b * 2 + o] = v + __ldg(&b3[o]);
    }
}

// =====================================================================
extern "C" void kernel_launch(void* const* d_in, const int* in_sizes, int n_in,
                              void* d_out, int out_size)
{
    const float* x     = (const float*)d_in[0];
    const float* p_w   = (const float*)d_in[1];
    const float* p_b   = (const float*)d_in[2];
    const float* dcn_w = (const float*)d_in[3];
    const float* dcn_b = (const float*)d_in[4];
    const float* w_ih  = (const float*)d_in[5];
    const float* w_hh  = (const float*)d_in[6];
    const float* b_ih  = (const float*)d_in[7];
    const float* b_hh  = (const float*)d_in[8];
    const float* w1    = (const float*)d_in[9];
    const float* b1    = (const float*)d_in[10];
    const float* w2    = (const float*)d_in[11];
    const float* b2    = (const float*)d_in[12];
    const float* w3    = (const float*)d_in[13];
    const float* b3    = (const float*)d_in[14];
    float* out = (float*)d_out;

    {
        int n = G3_ * GIN_;
        k_wprep<<<(n + 255) / 256, 256>>>(w_ih);
    }
    {
        int total   = B_ * H_ * WO_;
        int threads = 128;
        int blocks  = (total + threads - 1) / threads;
        k_deform<<<blocks, threads>>>(x, p_w, p_b, dcn_w, dcn_b);
    }
    {
        k_gemm<<<NTOK_ / TM_, 128>>>(b_ih);         // 510 blocks
    }
    {
        k_gru<<<B_, GH_>>>(w_hh, b_hh);
    }
    {
        k_scores<<<(HTOK_ + 127) / 128, 128>>>(w1, b1, w2, b2);  // 128 blocks
    }
    {
        k_pool<<<B_, 512>>>(w3, b3, out);
    }
}